// round 3
// baseline (speedup 1.0000x reference)
#include <cuda_runtime.h>
#include <cstdio>

// ---------------- problem constants ----------------
#define PN0 100000
#define PN1 50000
#define PN2 25000
#define PN3 12500
#define PB  8
#define PS  1024
#define C0 32
#define C1 64
#define C2 128
#define C3 256

// ---------------- scratch (device globals; no allocation allowed) ----------------
__device__ float g_x0[PN0 * C0];
__device__ float g_t0[PN0 * C0];
__device__ float g_x1[PN1 * C1];
__device__ float g_t1[PN1 * C1];
__device__ float g_x2[PN2 * C2];
__device__ float g_t2[PN2 * C2];
__device__ float g_x3[PN3 * C3];
__device__ float g_t3[PN3 * C3];

// ---------------- generic sparse conv: out[n,o] = (resid?) + relu(sum_k sum_c f[nbr[n,k],c]*W[k,c,o]) ----------------
// Block: 256 threads, M_TILE=32 nodes. Warp threads differ only in o -> all LDS are broadcasts.
template <int KK, int CIN, int COUT, bool RESID>
__global__ __launch_bounds__(256) void spconv_kernel(
    const float* __restrict__ f, const int* __restrict__ nbr,
    const float* __restrict__ W, const float* __restrict__ resid,
    float* __restrict__ out, int N)
{
    constexpr int M_TILE = 32;
    constexpr int OREP = 256 / COUT;       // node-groups per block
    constexpr int MT   = M_TILE / OREP;    // rows per thread

    __shared__ __align__(16) float As[M_TILE][CIN];
    __shared__ int s_idx[M_TILE * KK];

    const int tid = threadIdx.x;
    const int n0  = blockIdx.x * M_TILE;
    const int o   = tid % COUT;
    const int mg  = tid / COUT;

    // preload all neighbor indices for this node tile (contiguous in nbr)
    for (int i = tid; i < M_TILE * KK; i += 256) {
        int n = n0 + i / KK;
        s_idx[i] = (n < N) ? nbr[(size_t)n0 * KK + i] : 0;
    }

    float acc[MT];
#pragma unroll
    for (int mi = 0; mi < MT; mi++) acc[mi] = 0.f;

    for (int k = 0; k < KK; k++) {
        __syncthreads();
        // gather M_TILE neighbor rows into shared
        if constexpr (CIN % 4 == 0) {
            constexpr int C4 = CIN / 4;
            for (int i = tid; i < M_TILE * C4; i += 256) {
                int m = i / C4, c4 = i % C4;
                float4 v = __ldg((const float4*)(f + (size_t)s_idx[m * KK + k] * CIN) + c4);
                ((float4*)&As[m][0])[c4] = v;
            }
        } else {
            for (int i = tid; i < M_TILE * CIN; i += 256) {
                int m = i / CIN, c = i % CIN;
                As[m][c] = __ldg(f + (size_t)s_idx[m * KK + k] * CIN + c);
            }
        }
        __syncthreads();

        const float* Wk = W + (size_t)k * CIN * COUT;
        if constexpr (CIN % 4 == 0) {
            for (int c = 0; c < CIN; c += 4) {
                float w0 = __ldg(Wk + (size_t)(c + 0) * COUT + o);
                float w1 = __ldg(Wk + (size_t)(c + 1) * COUT + o);
                float w2 = __ldg(Wk + (size_t)(c + 2) * COUT + o);
                float w3 = __ldg(Wk + (size_t)(c + 3) * COUT + o);
#pragma unroll
                for (int mi = 0; mi < MT; mi++) {
                    float4 a = *(const float4*)&As[mg * MT + mi][c];
                    acc[mi] += a.x * w0 + a.y * w1 + a.z * w2 + a.w * w3;
                }
            }
        } else {
            for (int c = 0; c < CIN; c++) {
                float w = __ldg(Wk + (size_t)c * COUT + o);
#pragma unroll
                for (int mi = 0; mi < MT; mi++)
                    acc[mi] += As[mg * MT + mi][c] * w;
            }
        }
    }

#pragma unroll
    for (int mi = 0; mi < MT; mi++) {
        int n = n0 + mg * MT + mi;
        if (n < N) {
            float v = fmaxf(acc[mi], 0.f);
            if constexpr (RESID) v += resid[(size_t)n * COUT + o];
            out[(size_t)n * COUT + o] = v;
        }
    }
}

// ---------------- fused sparse decoder: compute u2/u1/u0/out only along seed chains ----------------
// Each block handles 4 seeds. All intermediates live in shared.
#define BSEED 4
__global__ __launch_bounds__(256) void decoder_kernel(
    const float* __restrict__ x0, const float* __restrict__ x1,
    const float* __restrict__ x2, const float* __restrict__ x3,
    const int* __restrict__ up0, const int* __restrict__ up1,
    const int* __restrict__ up2, const int* __restrict__ seed_idx,
    const float* __restrict__ Wu2, const float* __restrict__ Wu1,
    const float* __restrict__ Wu0, const float* __restrict__ Wout,
    float* __restrict__ out)
{
    __shared__ float sIn[BSEED][384];
    __shared__ float sMid[BSEED][256];
    __shared__ int sP[BSEED], sJ1[BSEED], sJ2[BSEED], sJ3[BSEED];

    const int tid = threadIdx.x;
    const int g0  = blockIdx.x * BSEED;

    if (tid < BSEED) {
        int p  = seed_idx[g0 + tid];
        int j1 = up0[p];
        int j2 = up1[j1];
        int j3 = up2[j2];
        sP[tid] = p; sJ1[tid] = j1; sJ2[tid] = j2; sJ3[tid] = j3;
    }
    __syncthreads();

    // stage in2 = [x3[j3] (256) | x2[j2] (128)]
    for (int i = tid; i < BSEED * 384; i += 256) {
        int s = i / 384, c = i % 384;
        sIn[s][c] = (c < 256) ? x3[(size_t)sJ3[s] * 256 + c]
                              : x2[(size_t)sJ2[s] * 128 + (c - 256)];
    }
    __syncthreads();

    // u2 = relu(in2 @ Wu2): 384 -> 256, o = tid
    {
        float a0 = 0.f, a1 = 0.f, a2 = 0.f, a3 = 0.f;
        const int o = tid;
        for (int c = 0; c < 384; c++) {
            float w = __ldg(Wu2 + (size_t)c * 256 + o);
            a0 += sIn[0][c] * w; a1 += sIn[1][c] * w;
            a2 += sIn[2][c] * w; a3 += sIn[3][c] * w;
        }
        sMid[0][o] = fmaxf(a0, 0.f); sMid[1][o] = fmaxf(a1, 0.f);
        sMid[2][o] = fmaxf(a2, 0.f); sMid[3][o] = fmaxf(a3, 0.f);
    }
    __syncthreads();

    // in1 = [u2 (256) | x1[j1] (64)] width 320
    for (int i = tid; i < BSEED * 320; i += 256) {
        int s = i / 320, c = i % 320;
        sIn[s][c] = (c < 256) ? sMid[s][c]
                              : x1[(size_t)sJ1[s] * 64 + (c - 256)];
    }
    __syncthreads();

    // u1 = relu(in1 @ Wu1): 320 -> 128; 512 outputs -> 2 per thread
    {
        const int o  = tid % 128;
        const int sh = tid / 128;   // 0 or 1: seeds {sh, sh+2}
        float a0 = 0.f, a1 = 0.f;
        for (int c = 0; c < 320; c++) {
            float w = __ldg(Wu1 + (size_t)c * 128 + o);
            a0 += sIn[sh][c] * w;
            a1 += sIn[sh + 2][c] * w;
        }
        __syncthreads();  // all sIn reads done before sMid overwrite? (sMid != sIn, but keep read/write of sMid ordered vs stage above)
        sMid[sh][o]     = fmaxf(a0, 0.f);
        sMid[sh + 2][o] = fmaxf(a1, 0.f);
    }
    __syncthreads();

    // in0 = [u1 (128) | x0[p] (32)] width 160
    for (int i = tid; i < BSEED * 160; i += 256) {
        int s = i / 160, c = i % 160;
        sIn[s][c] = (c < 128) ? sMid[s][c]
                              : x0[(size_t)sP[s] * 32 + (c - 128)];
    }
    __syncthreads();

    // u0 = relu(in0 @ Wu0): 160 -> 96; 384 outputs
    for (int i = tid; i < BSEED * 96; i += 256) {
        int s = i / 96, o = i % 96;
        float a = 0.f;
        for (int c = 0; c < 160; c++)
            a += sIn[s][c] * __ldg(Wu0 + (size_t)c * 96 + o);
        sMid[s][o] = fmaxf(a, 0.f);
    }
    __syncthreads();

    // out = u0 @ Wout: 96 -> 512 (no relu); write transposed [B, 512, S]
    for (int i = tid; i < BSEED * 512; i += 256) {
        int s = i / 512, o = i % 512;
        float a = 0.f;
        for (int c = 0; c < 96; c++)
            a += sMid[s][c] * __ldg(Wout + (size_t)c * 512 + o);
        int g = g0 + s;
        int b = g / PS, si = g % PS;
        out[(size_t)b * 512 * PS + (size_t)o * PS + si] = a;
    }
}

// ---------------- launch ----------------
extern "C" void kernel_launch(void* const* d_in, const int* in_sizes, int n_in,
                              void* d_out, int out_size)
{
    (void)in_sizes; (void)n_in; (void)out_size;
    const float* feats   = (const float*)d_in[0];
    const int*   nbr0    = (const int*)d_in[1];
    const int*   nbr1    = (const int*)d_in[2];
    const int*   nbr2    = (const int*)d_in[3];
    const int*   nbr3    = (const int*)d_in[4];
    const int*   down1   = (const int*)d_in[5];
    const int*   down2   = (const int*)d_in[6];
    const int*   down3   = (const int*)d_in[7];
    const int*   up2     = (const int*)d_in[8];
    const int*   up1     = (const int*)d_in[9];
    const int*   up0     = (const int*)d_in[10];
    const int*   seedidx = (const int*)d_in[11];
    const float* W_stem  = (const float*)d_in[12];
    const float* W_b0    = (const float*)d_in[13];
    const float* W_d1    = (const float*)d_in[14];
    const float* W_b1    = (const float*)d_in[15];
    const float* W_d2    = (const float*)d_in[16];
    const float* W_b2    = (const float*)d_in[17];
    const float* W_d3    = (const float*)d_in[18];
    const float* W_b3    = (const float*)d_in[19];
    const float* W_u2    = (const float*)d_in[20];
    const float* W_u1    = (const float*)d_in[21];
    const float* W_u0    = (const float*)d_in[22];
    const float* W_out   = (const float*)d_in[23];

    float *px0, *pt0, *px1, *pt1, *px2, *pt2, *px3, *pt3;
    cudaGetSymbolAddress((void**)&px0, g_x0);
    cudaGetSymbolAddress((void**)&pt0, g_t0);
    cudaGetSymbolAddress((void**)&px1, g_x1);
    cudaGetSymbolAddress((void**)&pt1, g_t1);
    cudaGetSymbolAddress((void**)&px2, g_x2);
    cudaGetSymbolAddress((void**)&pt2, g_t2);
    cudaGetSymbolAddress((void**)&px3, g_x3);
    cudaGetSymbolAddress((void**)&pt3, g_t3);

    const int g0 = (PN0 + 31) / 32;
    const int g1 = (PN1 + 31) / 32;
    const int g2 = (PN2 + 31) / 32;
    const int g3 = (PN3 + 31) / 32;

    // encoder
    spconv_kernel<27, 3,   C0, false><<<g0, 256>>>(feats, nbr0, W_stem, nullptr, px0, PN0);
    spconv_kernel<27, C0,  C0, true ><<<g0, 256>>>(px0,  nbr0, W_b0,  px0, pt0, PN0);
    spconv_kernel<8,  C0,  C1, false><<<g1, 256>>>(pt0,  down1, W_d1, nullptr, px1, PN1);
    spconv_kernel<27, C1,  C1, true ><<<g1, 256>>>(px1,  nbr1, W_b1,  px1, pt1, PN1);
    spconv_kernel<8,  C1,  C2, false><<<g2, 256>>>(pt1,  down2, W_d2, nullptr, px2, PN2);
    spconv_kernel<27, C2,  C2, true ><<<g2, 256>>>(px2,  nbr2, W_b2,  px2, pt2, PN2);
    spconv_kernel<8,  C2,  C3, false><<<g3, 256>>>(pt2,  down3, W_d3, nullptr, px3, PN3);
    spconv_kernel<27, C3,  C3, true ><<<g3, 256>>>(px3,  nbr3, W_b3,  px3, pt3, PN3);

    // fused sparse decoder over seed chains only
    decoder_kernel<<<(PB * PS) / BSEED, 256>>>(
        pt0, pt1, pt2, pt3, up0, up1, up2, seedidx,
        W_u2, W_u1, W_u0, W_out, (float*)d_out);
}

// round 4
// speedup vs baseline: 2.8664x; 2.8664x over previous
#include <cuda_runtime.h>
#include <cstdint>

// ---------------- problem constants ----------------
#define PN0 100000
#define PN1 50000
#define PN2 25000
#define PN3 12500
#define PB  8
#define PS  1024
#define C0 32
#define C1 64
#define C2 128
#define C3 256

// ---------------- scratch (device globals; no allocation allowed) ----------------
__device__ float g_x0[PN0 * C0];
__device__ float g_t0[PN0 * C0];
__device__ float g_x1[PN1 * C1];
__device__ float g_t1[PN1 * C1];
__device__ float g_x2[PN2 * C2];
__device__ float g_t2[PN2 * C2];
__device__ float g_x3[PN3 * C3];
__device__ float g_t3[PN3 * C3];

// ---------------- helpers ----------------
__device__ __forceinline__ float tf32_rna(float x) {
    uint32_t u;
    asm("cvt.rna.tf32.f32 %0, %1;" : "=r"(u) : "f"(x));
    return __uint_as_float(u);
}

__device__ __forceinline__ void mma_tf32(float d[4], const uint32_t a[4],
                                         uint32_t b0, uint32_t b1) {
    asm volatile(
        "mma.sync.aligned.m16n8k8.row.col.f32.tf32.tf32.f32 "
        "{%0,%1,%2,%3}, {%4,%5,%6,%7}, {%8,%9}, {%0,%1,%2,%3};\n"
        : "+f"(d[0]), "+f"(d[1]), "+f"(d[2]), "+f"(d[3])
        : "r"(a[0]), "r"(a[1]), "r"(a[2]), "r"(a[3]), "r"(b0), "r"(b1));
}

// ---------------- tensor-core implicit gather-GEMM sparse conv ----------------
// out[n,o] = (resid?) + relu( sum_k sum_c f[nbr[n,k],c] * W[k,c,o] )
// Block: 256 threads / 8 warps. Tile: 128 rows x NT cols. tf32 mma.sync.
template <int KK, int CIN, int COUT, int NT, bool RESID>
__global__ __launch_bounds__(256) void spconv_mma(
    const float* __restrict__ f, const int* __restrict__ nbr,
    const float* __restrict__ W, const float* __restrict__ resid,
    float* __restrict__ out, int N)
{
    constexpr int WM = (NT == 32) ? 8 : 4;     // warps along M
    constexpr int WN = 8 / WM;                 // warps along N
    constexpr int WTM = 128 / WM;              // warp tile M (16 or 32)
    constexpr int WTN = NT / WN;               // warp tile N
    constexpr int MF = WTM / 16;               // m-fragments per warp
    constexpr int NF = WTN / 8;                // n-fragments per warp
    constexpr int CCHUNK = (CIN < 64) ? CIN : 64;
    constexpr int NCH = CIN / CCHUNK;
    constexpr int APITCH = CCHUNK + 4;         // conflict-free A frag loads
    constexpr int BPITCH = NT + 8;             // conflict-free B frag loads

    extern __shared__ float smem[];
    float* sA = smem;                              // [128][APITCH]
    float* sB = sA + 128 * APITCH;                 // [CCHUNK][BPITCH]
    int*   sIdx = (int*)(sB + CCHUNK * BPITCH);    // [128*KK]

    const int tid  = threadIdx.x;
    const int warp = tid >> 5;
    const int lane = tid & 31;
    const int gId  = lane >> 2;   // 0..7
    const int tig  = lane & 3;    // 0..3
    const int wm = warp % WM;
    const int wn = warp / WM;
    const int n0  = blockIdx.x * 128;
    const int nt0 = blockIdx.y * NT;

    // preload all neighbor indices for this 128-row tile
    for (int i = tid; i < 128 * KK; i += 256) {
        int n = n0 + i / KK;
        sIdx[i] = (n < N) ? nbr[(size_t)n0 * KK + i] : 0;
    }

    float acc[MF][NF][4];
#pragma unroll
    for (int mf = 0; mf < MF; mf++)
#pragma unroll
        for (int nf = 0; nf < NF; nf++)
#pragma unroll
            for (int i = 0; i < 4; i++) acc[mf][nf][i] = 0.f;

    for (int k = 0; k < KK; k++) {
        for (int ch = 0; ch < NCH; ch++) {
            __syncthreads();
            // ---- gather A chunk: 128 rows x CCHUNK channels (tf32-rounded) ----
            constexpr int C4 = CCHUNK / 4;
            for (int i = tid; i < 128 * C4; i += 256) {
                int m = i / C4, c4 = i % C4;
                float4 v = __ldg((const float4*)(f + (size_t)sIdx[m * KK + k] * CIN
                                                 + ch * CCHUNK) + c4);
                float* dst = sA + m * APITCH + c4 * 4;
                dst[0] = tf32_rna(v.x); dst[1] = tf32_rna(v.y);
                dst[2] = tf32_rna(v.z); dst[3] = tf32_rna(v.w);
            }
            // ---- stage B chunk: CCHUNK x NT weight slice ----
            const float* Wk = W + ((size_t)k * CIN + ch * CCHUNK) * COUT + nt0;
            constexpr int N4 = NT / 4;
            for (int i = tid; i < CCHUNK * N4; i += 256) {
                int c = i / N4, o4 = i % N4;
                float4 v = __ldg((const float4*)(Wk + (size_t)c * COUT) + o4);
                float* dst = sB + c * BPITCH + o4 * 4;
                dst[0] = tf32_rna(v.x); dst[1] = tf32_rna(v.y);
                dst[2] = tf32_rna(v.z); dst[3] = tf32_rna(v.w);
            }
            __syncthreads();

            // ---- mma over this chunk ----
#pragma unroll
            for (int k8 = 0; k8 < CCHUNK / 8; k8++) {
                uint32_t a[MF][4];
#pragma unroll
                for (int mf = 0; mf < MF; mf++) {
                    const float* ap = sA + (wm * WTM + mf * 16 + gId) * APITCH
                                    + k8 * 8 + tig;
                    a[mf][0] = __float_as_uint(ap[0]);
                    a[mf][1] = __float_as_uint(ap[8 * APITCH]);
                    a[mf][2] = __float_as_uint(ap[4]);
                    a[mf][3] = __float_as_uint(ap[8 * APITCH + 4]);
                }
#pragma unroll
                for (int nf = 0; nf < NF; nf++) {
                    const float* bp = sB + (k8 * 8 + tig) * BPITCH
                                    + wn * WTN + nf * 8 + gId;
                    uint32_t b0 = __float_as_uint(bp[0]);
                    uint32_t b1 = __float_as_uint(bp[4 * BPITCH]);
#pragma unroll
                    for (int mf = 0; mf < MF; mf++)
                        mma_tf32(acc[mf][nf], a[mf], b0, b1);
                }
            }
        }
    }

    // ---- epilogue: relu (+ residual), float2 stores ----
#pragma unroll
    for (int mf = 0; mf < MF; mf++) {
        const int r = wm * WTM + mf * 16 + gId;
#pragma unroll
        for (int nf = 0; nf < NF; nf++) {
            const int o = nt0 + wn * WTN + nf * 8 + 2 * tig;
            int n = n0 + r;
            if (n < N) {
                float2 v;
                v.x = fmaxf(acc[mf][nf][0], 0.f);
                v.y = fmaxf(acc[mf][nf][1], 0.f);
                if constexpr (RESID) {
                    float2 rr = *(const float2*)(resid + (size_t)n * COUT + o);
                    v.x += rr.x; v.y += rr.y;
                }
                *(float2*)(out + (size_t)n * COUT + o) = v;
            }
            int n2 = n0 + r + 8;
            if (n2 < N) {
                float2 v;
                v.x = fmaxf(acc[mf][nf][2], 0.f);
                v.y = fmaxf(acc[mf][nf][3], 0.f);
                if constexpr (RESID) {
                    float2 rr = *(const float2*)(resid + (size_t)n2 * COUT + o);
                    v.x += rr.x; v.y += rr.y;
                }
                *(float2*)(out + (size_t)n2 * COUT + o) = v;
            }
        }
    }
}

constexpr int mma_smem_bytes(int KK, int CIN, int NT) {
    int cc = (CIN < 64) ? CIN : 64;
    return (128 * (cc + 4) + cc * (NT + 8)) * 4 + 128 * KK * 4;
}

// ---------------- scalar fp32 conv for the stem (CIN=3) ----------------
template <int KK, int CIN, int COUT, bool RESID>
__global__ __launch_bounds__(256) void spconv_kernel(
    const float* __restrict__ f, const int* __restrict__ nbr,
    const float* __restrict__ W, const float* __restrict__ resid,
    float* __restrict__ out, int N)
{
    constexpr int M_TILE = 32;
    constexpr int OREP = 256 / COUT;
    constexpr int MT   = M_TILE / OREP;

    __shared__ __align__(16) float As[M_TILE][CIN];
    __shared__ int s_idx[M_TILE * KK];

    const int tid = threadIdx.x;
    const int n0  = blockIdx.x * M_TILE;
    const int o   = tid % COUT;
    const int mg  = tid / COUT;

    for (int i = tid; i < M_TILE * KK; i += 256) {
        int n = n0 + i / KK;
        s_idx[i] = (n < N) ? nbr[(size_t)n0 * KK + i] : 0;
    }

    float acc[MT];
#pragma unroll
    for (int mi = 0; mi < MT; mi++) acc[mi] = 0.f;

    for (int k = 0; k < KK; k++) {
        __syncthreads();
        for (int i = tid; i < M_TILE * CIN; i += 256) {
            int m = i / CIN, c = i % CIN;
            As[m][c] = __ldg(f + (size_t)s_idx[m * KK + k] * CIN + c);
        }
        __syncthreads();
        const float* Wk = W + (size_t)k * CIN * COUT;
        for (int c = 0; c < CIN; c++) {
            float w = __ldg(Wk + (size_t)c * COUT + o);
#pragma unroll
            for (int mi = 0; mi < MT; mi++)
                acc[mi] += As[mg * MT + mi][c] * w;
        }
    }

#pragma unroll
    for (int mi = 0; mi < MT; mi++) {
        int n = n0 + mg * MT + mi;
        if (n < N) {
            float v = fmaxf(acc[mi], 0.f);
            if constexpr (RESID) v += resid[(size_t)n * COUT + o];
            out[(size_t)n * COUT + o] = v;
        }
    }
}

// ---------------- fused sparse decoder over seed chains ----------------
#define BSEED 4
__global__ __launch_bounds__(256) void decoder_kernel(
    const float* __restrict__ x0, const float* __restrict__ x1,
    const float* __restrict__ x2, const float* __restrict__ x3,
    const int* __restrict__ up0, const int* __restrict__ up1,
    const int* __restrict__ up2, const int* __restrict__ seed_idx,
    const float* __restrict__ Wu2, const float* __restrict__ Wu1,
    const float* __restrict__ Wu0, const float* __restrict__ Wout,
    float* __restrict__ out)
{
    __shared__ float sIn[BSEED][384];
    __shared__ float sMid[BSEED][256];
    __shared__ int sP[BSEED], sJ1[BSEED], sJ2[BSEED], sJ3[BSEED];

    const int tid = threadIdx.x;
    const int g0  = blockIdx.x * BSEED;

    if (tid < BSEED) {
        int p  = seed_idx[g0 + tid];
        int j1 = up0[p];
        int j2 = up1[j1];
        int j3 = up2[j2];
        sP[tid] = p; sJ1[tid] = j1; sJ2[tid] = j2; sJ3[tid] = j3;
    }
    __syncthreads();

    for (int i = tid; i < BSEED * 384; i += 256) {
        int s = i / 384, c = i % 384;
        sIn[s][c] = (c < 256) ? x3[(size_t)sJ3[s] * 256 + c]
                              : x2[(size_t)sJ2[s] * 128 + (c - 256)];
    }
    __syncthreads();

    {
        float a0 = 0.f, a1 = 0.f, a2 = 0.f, a3 = 0.f;
        const int o = tid;
        for (int c = 0; c < 384; c++) {
            float w = __ldg(Wu2 + (size_t)c * 256 + o);
            a0 += sIn[0][c] * w; a1 += sIn[1][c] * w;
            a2 += sIn[2][c] * w; a3 += sIn[3][c] * w;
        }
        sMid[0][o] = fmaxf(a0, 0.f); sMid[1][o] = fmaxf(a1, 0.f);
        sMid[2][o] = fmaxf(a2, 0.f); sMid[3][o] = fmaxf(a3, 0.f);
    }
    __syncthreads();

    for (int i = tid; i < BSEED * 320; i += 256) {
        int s = i / 320, c = i % 320;
        sIn[s][c] = (c < 256) ? sMid[s][c]
                              : x1[(size_t)sJ1[s] * 64 + (c - 256)];
    }
    __syncthreads();

    {
        const int o  = tid % 128;
        const int sh = tid / 128;
        float a0 = 0.f, a1 = 0.f;
        for (int c = 0; c < 320; c++) {
            float w = __ldg(Wu1 + (size_t)c * 128 + o);
            a0 += sIn[sh][c] * w;
            a1 += sIn[sh + 2][c] * w;
        }
        __syncthreads();
        sMid[sh][o]     = fmaxf(a0, 0.f);
        sMid[sh + 2][o] = fmaxf(a1, 0.f);
    }
    __syncthreads();

    for (int i = tid; i < BSEED * 160; i += 256) {
        int s = i / 160, c = i % 160;
        sIn[s][c] = (c < 128) ? sMid[s][c]
                              : x0[(size_t)sP[s] * 32 + (c - 128)];
    }
    __syncthreads();

    for (int i = tid; i < BSEED * 96; i += 256) {
        int s = i / 96, o = i % 96;
        float a = 0.f;
        for (int c = 0; c < 160; c++)
            a += sIn[s][c] * __ldg(Wu0 + (size_t)c * 96 + o);
        sMid[s][o] = fmaxf(a, 0.f);
    }
    __syncthreads();

    for (int i = tid; i < BSEED * 512; i += 256) {
        int s = i / 512, o = i % 512;
        float a = 0.f;
        for (int c = 0; c < 96; c++)
            a += sMid[s][c] * __ldg(Wout + (size_t)c * 512 + o);
        int g = g0 + s;
        int b = g / PS, si = g % PS;
        out[(size_t)b * 512 * PS + (size_t)o * PS + si] = a;
    }
}

// ---------------- launch ----------------
extern "C" void kernel_launch(void* const* d_in, const int* in_sizes, int n_in,
                              void* d_out, int out_size)
{
    (void)in_sizes; (void)n_in; (void)out_size;
    const float* feats   = (const float*)d_in[0];
    const int*   nbr0    = (const int*)d_in[1];
    const int*   nbr1    = (const int*)d_in[2];
    const int*   nbr2    = (const int*)d_in[3];
    const int*   nbr3    = (const int*)d_in[4];
    const int*   down1   = (const int*)d_in[5];
    const int*   down2   = (const int*)d_in[6];
    const int*   down3   = (const int*)d_in[7];
    const int*   up2     = (const int*)d_in[8];
    const int*   up1     = (const int*)d_in[9];
    const int*   up0     = (const int*)d_in[10];
    const int*   seedidx = (const int*)d_in[11];
    const float* W_stem  = (const float*)d_in[12];
    const float* W_b0    = (const float*)d_in[13];
    const float* W_d1    = (const float*)d_in[14];
    const float* W_b1    = (const float*)d_in[15];
    const float* W_d2    = (const float*)d_in[16];
    const float* W_b2    = (const float*)d_in[17];
    const float* W_d3    = (const float*)d_in[18];
    const float* W_b3    = (const float*)d_in[19];
    const float* W_u2    = (const float*)d_in[20];
    const float* W_u1    = (const float*)d_in[21];
    const float* W_u0    = (const float*)d_in[22];
    const float* W_out   = (const float*)d_in[23];

    float *px0, *pt0, *px1, *pt1, *px2, *pt2, *px3, *pt3;
    cudaGetSymbolAddress((void**)&px0, g_x0);
    cudaGetSymbolAddress((void**)&pt0, g_t0);
    cudaGetSymbolAddress((void**)&px1, g_x1);
    cudaGetSymbolAddress((void**)&pt1, g_t1);
    cudaGetSymbolAddress((void**)&px2, g_x2);
    cudaGetSymbolAddress((void**)&pt2, g_t2);
    cudaGetSymbolAddress((void**)&px3, g_x3);
    cudaGetSymbolAddress((void**)&pt3, g_t3);

    // dynamic smem sizes + attributes (idempotent, capture-safe)
    constexpr int sm_b0 = mma_smem_bytes(27, 32, 32);
    constexpr int sm_d1 = mma_smem_bytes(8, 32, 64);
    constexpr int sm_b1 = mma_smem_bytes(27, 64, 64);
    constexpr int sm_d2 = mma_smem_bytes(8, 64, 128);
    constexpr int sm_b2 = mma_smem_bytes(27, 128, 128);
    constexpr int sm_d3 = mma_smem_bytes(8, 128, 128);
    constexpr int sm_b3 = mma_smem_bytes(27, 256, 128);

    cudaFuncSetAttribute((const void*)spconv_mma<27, 32, 32, 32, true>,
                         cudaFuncAttributeMaxDynamicSharedMemorySize, sm_b0);
    cudaFuncSetAttribute((const void*)spconv_mma<8, 32, 64, 64, false>,
                         cudaFuncAttributeMaxDynamicSharedMemorySize, sm_d1);
    cudaFuncSetAttribute((const void*)spconv_mma<27, 64, 64, 64, true>,
                         cudaFuncAttributeMaxDynamicSharedMemorySize, sm_b1);
    cudaFuncSetAttribute((const void*)spconv_mma<8, 64, 128, 128, false>,
                         cudaFuncAttributeMaxDynamicSharedMemorySize, sm_d2);
    cudaFuncSetAttribute((const void*)spconv_mma<27, 128, 128, 128, true>,
                         cudaFuncAttributeMaxDynamicSharedMemorySize, sm_b2);
    cudaFuncSetAttribute((const void*)spconv_mma<8, 128, 256, 128, false>,
                         cudaFuncAttributeMaxDynamicSharedMemorySize, sm_d3);
    cudaFuncSetAttribute((const void*)spconv_mma<27, 256, 256, 128, true>,
                         cudaFuncAttributeMaxDynamicSharedMemorySize, sm_b3);

    const int gm0 = (PN0 + 127) / 128;
    const int gm1 = (PN1 + 127) / 128;
    const int gm2 = (PN2 + 127) / 128;
    const int gm3 = (PN3 + 127) / 128;

    // stem: scalar fp32 (CIN=3, cheap)
    spconv_kernel<27, 3, C0, false><<<(PN0 + 31) / 32, 256>>>(
        feats, nbr0, W_stem, nullptr, px0, PN0);

    // encoder: tensor-core tf32 gather-GEMMs
    spconv_mma<27, 32, 32, 32, true><<<dim3(gm0, 1), 256, sm_b0>>>(
        px0, nbr0, W_b0, px0, pt0, PN0);
    spconv_mma<8, 32, 64, 64, false><<<dim3(gm1, 1), 256, sm_d1>>>(
        pt0, down1, W_d1, nullptr, px1, PN1);
    spconv_mma<27, 64, 64, 64, true><<<dim3(gm1, 1), 256, sm_b1>>>(
        px1, nbr1, W_b1, px1, pt1, PN1);
    spconv_mma<8, 64, 128, 128, false><<<dim3(gm2, 1), 256, sm_d2>>>(
        pt1, down2, W_d2, nullptr, px2, PN2);
    spconv_mma<27, 128, 128, 128, true><<<dim3(gm2, 1), 256, sm_b2>>>(
        px2, nbr2, W_b2, px2, pt2, PN2);
    spconv_mma<8, 128, 256, 128, false><<<dim3(gm3, 2), 256, sm_d3>>>(
        pt2, down3, W_d3, nullptr, px3, PN3);
    spconv_mma<27, 256, 256, 128, true><<<dim3(gm3, 2), 256, sm_b3>>>(
        px3, nbr3, W_b3, px3, pt3, PN3);

    // fused sparse decoder over seed chains only
    decoder_kernel<<<(PB * PS) / BSEED, 256>>>(
        pt0, pt1, pt2, pt3, up0, up1, up2, seedidx,
        W_u2, W_u1, W_u0, W_out, (float*)d_out);
}

// round 6
// speedup vs baseline: 3.0503x; 1.0642x over previous
#include <cuda_runtime.h>
#include <cstdint>

// ---------------- problem constants ----------------
#define PN0 100000
#define PN1 50000
#define PN2 25000
#define PN3 12500
#define PB  8
#define PS  1024
#define C0 32
#define C1 64
#define C2 128
#define C3 256

// ---------------- scratch (device globals; no allocation allowed) ----------------
__device__ float g_x0[PN0 * C0];
__device__ float g_t0[PN0 * C0];
__device__ float g_x1[PN1 * C1];
__device__ float g_t1[PN1 * C1];
__device__ float g_x2[PN2 * C2];
__device__ float g_t2[PN2 * C2];
__device__ float g_x3[PN3 * C3];
__device__ float g_t3[PN3 * C3];

// pre-converted tf32 weights
__device__ float g_wb0[27 * 32 * 32];
__device__ float g_wd1[8 * 32 * 64];
__device__ float g_wb1[27 * 64 * 64];
__device__ float g_wd2[8 * 64 * 128];
__device__ float g_wb2[27 * 128 * 128];
__device__ float g_wd3[8 * 128 * 256];
__device__ float g_wb3[27 * 256 * 256];

// ---------------- helpers ----------------
__device__ __forceinline__ float tf32_rna(float x) {
    uint32_t u;
    asm("cvt.rna.tf32.f32 %0, %1;" : "=r"(u) : "f"(x));
    return __uint_as_float(u);
}

__device__ __forceinline__ void mma_tf32(float d[4], const uint32_t a[4],
                                         uint32_t b0, uint32_t b1) {
    asm volatile(
        "mma.sync.aligned.m16n8k8.row.col.f32.tf32.tf32.f32 "
        "{%0,%1,%2,%3}, {%4,%5,%6,%7}, {%8,%9}, {%0,%1,%2,%3};\n"
        : "+f"(d[0]), "+f"(d[1]), "+f"(d[2]), "+f"(d[3])
        : "r"(a[0]), "r"(a[1]), "r"(a[2]), "r"(a[3]), "r"(b0), "r"(b1));
}

__device__ __forceinline__ void cp_async16(float* dst_smem, const float* src) {
    uint32_t d = (uint32_t)__cvta_generic_to_shared(dst_smem);
    asm volatile("cp.async.cg.shared.global [%0], [%1], 16;" :: "r"(d), "l"(src));
}
__device__ __forceinline__ void cp_commit() {
    asm volatile("cp.async.commit_group;");
}
template <int NN>
__device__ __forceinline__ void cp_wait() {
    asm volatile("cp.async.wait_group %0;" :: "n"(NN));
}

// ---------------- weight tf32 conversion ----------------
__global__ void cvt_tf32_kernel(const float* __restrict__ src,
                                float* __restrict__ dst, int n) {
    int i = blockIdx.x * 256 + threadIdx.x;
    if (i < n) dst[i] = tf32_rna(src[i]);
}

// ---------------- tensor-core implicit gather-GEMM sparse conv ----------------
// out[n,o] = (resid?) + relu( sum_k sum_c f[nbr[n,k],c] * W[k,c,o] )
// f and Wt are pre-tf32-rounded -> staging is a raw cp.async copy.
// Double-buffered cp.async pipeline over (k, channel-chunk) stages.
template <int KK, int CIN, int COUT, int NT, bool RESID, bool RND>
__global__ __launch_bounds__(256) void spconv_mma(
    const float* __restrict__ f, const int* __restrict__ nbr,
    const float* __restrict__ Wt, const float* __restrict__ resid,
    float* __restrict__ out, int N)
{
    constexpr int WM = (NT == 32) ? 8 : 4;
    constexpr int WN = 8 / WM;
    constexpr int WTM = 128 / WM;
    constexpr int WTN = NT / WN;
    constexpr int MF = WTM / 16;
    constexpr int NF = WTN / 8;
    constexpr int CC  = (CIN < 64) ? CIN : 64;
    constexpr int NCH = CIN / CC;
    constexpr int NSTAGE = KK * NCH;
    constexpr int AP = CC + 4;    // conflict-free A frag loads, 16B-multiple pitch
    constexpr int BP = NT + 4;    // conflict-free B frag loads, 16B-multiple pitch
    constexpr int C4 = CC / 4;
    constexpr int N4 = NT / 4;

    extern __shared__ float smem[];
    float* sA0 = smem;                     // [2][128][AP]
    float* sB0 = smem + 2 * 128 * AP;      // [2][CC][BP]

    const int tid  = threadIdx.x;
    const int warp = tid >> 5;
    const int lane = tid & 31;
    const int gId  = lane >> 2;
    const int tig  = lane & 3;
    const int wm = warp % WM;
    const int wn = warp / WM;
    const int n0  = blockIdx.x * 128;
    const int nt0 = blockIdx.y * NT;

    // ---- stage issue: gather A chunk + copy B chunk into buffer ----
    auto stage = [&](int buf, int s) {
        const int k = s / NCH, ch = s % NCH;
        float* dA = sA0 + buf * 128 * AP;
        float* dB = sB0 + buf * CC * BP;
#pragma unroll
        for (int i = tid; i < 128 * C4; i += 256) {
            int row = i / C4, c4 = i % C4;
            int n = n0 + row;
            int idx = (n < N) ? __ldg(nbr + (size_t)n * KK + k) : 0;
            cp_async16(dA + row * AP + c4 * 4,
                       f + (size_t)idx * CIN + ch * CC + c4 * 4);
        }
        const float* Wk = Wt + ((size_t)k * CIN + ch * CC) * COUT + nt0;
#pragma unroll
        for (int i = tid; i < CC * N4; i += 256) {
            int r = i / N4, o4 = i % N4;
            cp_async16(dB + r * BP + o4 * 4, Wk + (size_t)r * COUT + o4 * 4);
        }
        cp_commit();
    };

    float acc[MF][NF][4];
#pragma unroll
    for (int mf = 0; mf < MF; mf++)
#pragma unroll
        for (int nf = 0; nf < NF; nf++)
#pragma unroll
            for (int i = 0; i < 4; i++) acc[mf][nf][i] = 0.f;

    stage(0, 0);

    for (int s = 0; s < NSTAGE; s++) {
        const int buf = s & 1;
        if (s + 1 < NSTAGE) {
            stage(buf ^ 1, s + 1);
            cp_wait<1>();
        } else {
            cp_wait<0>();
        }
        __syncthreads();

        const float* A = sA0 + buf * 128 * AP;
        const float* B = sB0 + buf * CC * BP;
#pragma unroll
        for (int k8 = 0; k8 < CC / 8; k8++) {
            uint32_t a[MF][4];
#pragma unroll
            for (int mf = 0; mf < MF; mf++) {
                const float* ap = A + (wm * WTM + mf * 16 + gId) * AP + k8 * 8 + tig;
                a[mf][0] = __float_as_uint(ap[0]);
                a[mf][1] = __float_as_uint(ap[8 * AP]);
                a[mf][2] = __float_as_uint(ap[4]);
                a[mf][3] = __float_as_uint(ap[8 * AP + 4]);
            }
#pragma unroll
            for (int nf = 0; nf < NF; nf++) {
                const float* bp = B + (k8 * 8 + tig) * BP + wn * WTN + nf * 8 + gId;
                uint32_t b0 = __float_as_uint(bp[0]);
                uint32_t b1 = __float_as_uint(bp[4 * BP]);
#pragma unroll
                for (int mf = 0; mf < MF; mf++)
                    mma_tf32(acc[mf][nf], a[mf], b0, b1);
            }
        }
        __syncthreads();
    }

    // ---- epilogue: relu (+ residual), optional tf32 rounding, float2 stores ----
#pragma unroll
    for (int mf = 0; mf < MF; mf++) {
        const int r = wm * WTM + mf * 16 + gId;
#pragma unroll
        for (int nf = 0; nf < NF; nf++) {
            const int o = nt0 + wn * WTN + nf * 8 + 2 * tig;
            int n = n0 + r;
            if (n < N) {
                float2 v;
                v.x = fmaxf(acc[mf][nf][0], 0.f);
                v.y = fmaxf(acc[mf][nf][1], 0.f);
                if constexpr (RESID) {
                    float2 rr = *(const float2*)(resid + (size_t)n * COUT + o);
                    v.x += rr.x; v.y += rr.y;
                }
                if constexpr (RND) { v.x = tf32_rna(v.x); v.y = tf32_rna(v.y); }
                *(float2*)(out + (size_t)n * COUT + o) = v;
            }
            int n2 = n0 + r + 8;
            if (n2 < N) {
                float2 v;
                v.x = fmaxf(acc[mf][nf][2], 0.f);
                v.y = fmaxf(acc[mf][nf][3], 0.f);
                if constexpr (RESID) {
                    float2 rr = *(const float2*)(resid + (size_t)n2 * COUT + o);
                    v.x += rr.x; v.y += rr.y;
                }
                if constexpr (RND) { v.x = tf32_rna(v.x); v.y = tf32_rna(v.y); }
                *(float2*)(out + (size_t)n2 * COUT + o) = v;
            }
        }
    }
}

constexpr int mma_smem_bytes(int CIN, int NT) {
    int cc = (CIN < 64) ? CIN : 64;
    return (2 * 128 * (cc + 4) + 2 * cc * (NT + 4)) * 4;
}

// ---------------- scalar fp32 conv for the stem (CIN=3), tf32-rounded output ----------------
template <int KK, int CIN, int COUT>
__global__ __launch_bounds__(256) void spconv_stem(
    const float* __restrict__ f, const int* __restrict__ nbr,
    const float* __restrict__ W, float* __restrict__ out, int N)
{
    constexpr int M_TILE = 32;
    constexpr int OREP = 256 / COUT;
    constexpr int MT   = M_TILE / OREP;

    __shared__ __align__(16) float As[M_TILE][CIN];
    __shared__ int s_idx[M_TILE * KK];

    const int tid = threadIdx.x;
    const int n0  = blockIdx.x * M_TILE;
    const int o   = tid % COUT;
    const int mg  = tid / COUT;

    for (int i = tid; i < M_TILE * KK; i += 256) {
        int n = n0 + i / KK;
        s_idx[i] = (n < N) ? nbr[(size_t)n0 * KK + i] : 0;
    }

    float acc[MT];
#pragma unroll
    for (int mi = 0; mi < MT; mi++) acc[mi] = 0.f;

    for (int k = 0; k < KK; k++) {
        __syncthreads();
        for (int i = tid; i < M_TILE * CIN; i += 256) {
            int m = i / CIN, c = i % CIN;
            As[m][c] = __ldg(f + (size_t)s_idx[m * KK + k] * CIN + c);
        }
        __syncthreads();
        const float* Wk = W + (size_t)k * CIN * COUT;
        for (int c = 0; c < CIN; c++) {
            float w = __ldg(Wk + (size_t)c * COUT + o);
#pragma unroll
            for (int mi = 0; mi < MT; mi++)
                acc[mi] += As[mg * MT + mi][c] * w;
        }
    }

#pragma unroll
    for (int mi = 0; mi < MT; mi++) {
        int n = n0 + mg * MT + mi;
        if (n < N)
            out[(size_t)n * COUT + o] = tf32_rna(fmaxf(acc[mi], 0.f));
    }
}

// ---------------- fused sparse decoder over seed chains ----------------
#define BSEED 4
__global__ __launch_bounds__(256) void decoder_kernel(
    const float* __restrict__ x0, const float* __restrict__ x1,
    const float* __restrict__ x2, const float* __restrict__ x3,
    const int* __restrict__ up0, const int* __restrict__ up1,
    const int* __restrict__ up2, const int* __restrict__ seed_idx,
    const float* __restrict__ Wu2, const float* __restrict__ Wu1,
    const float* __restrict__ Wu0, const float* __restrict__ Wout,
    float* __restrict__ out)
{
    __shared__ float sIn[BSEED][384];
    __shared__ float sMid[BSEED][256];
    __shared__ int sP[BSEED], sJ1[BSEED], sJ2[BSEED], sJ3[BSEED];

    const int tid = threadIdx.x;
    const int g0  = blockIdx.x * BSEED;

    if (tid < BSEED) {
        int p  = seed_idx[g0 + tid];
        int j1 = up0[p];
        int j2 = up1[j1];
        int j3 = up2[j2];
        sP[tid] = p; sJ1[tid] = j1; sJ2[tid] = j2; sJ3[tid] = j3;
    }
    __syncthreads();

    for (int i = tid; i < BSEED * 384; i += 256) {
        int s = i / 384, c = i % 384;
        sIn[s][c] = (c < 256) ? x3[(size_t)sJ3[s] * 256 + c]
                              : x2[(size_t)sJ2[s] * 128 + (c - 256)];
    }
    __syncthreads();

    {
        float a0 = 0.f, a1 = 0.f, a2 = 0.f, a3 = 0.f;
        const int o = tid;
        for (int c = 0; c < 384; c++) {
            float w = __ldg(Wu2 + (size_t)c * 256 + o);
            a0 += sIn[0][c] * w; a1 += sIn[1][c] * w;
            a2 += sIn[2][c] * w; a3 += sIn[3][c] * w;
        }
        sMid[0][o] = fmaxf(a0, 0.f); sMid[1][o] = fmaxf(a1, 0.f);
        sMid[2][o] = fmaxf(a2, 0.f); sMid[3][o] = fmaxf(a3, 0.f);
    }
    __syncthreads();

    for (int i = tid; i < BSEED * 320; i += 256) {
        int s = i / 320, c = i % 320;
        sIn[s][c] = (c < 256) ? sMid[s][c]
                              : x1[(size_t)sJ1[s] * 64 + (c - 256)];
    }
    __syncthreads();

    {
        const int o  = tid % 128;
        const int sh = tid / 128;
        float a0 = 0.f, a1 = 0.f;
        for (int c = 0; c < 320; c++) {
            float w = __ldg(Wu1 + (size_t)c * 128 + o);
            a0 += sIn[sh][c] * w;
            a1 += sIn[sh + 2][c] * w;
        }
        __syncthreads();
        sMid[sh][o]     = fmaxf(a0, 0.f);
        sMid[sh + 2][o] = fmaxf(a1, 0.f);
    }
    __syncthreads();

    for (int i = tid; i < BSEED * 160; i += 256) {
        int s = i / 160, c = i % 160;
        sIn[s][c] = (c < 128) ? sMid[s][c]
                              : x0[(size_t)sP[s] * 32 + (c - 128)];
    }
    __syncthreads();

    for (int i = tid; i < BSEED * 96; i += 256) {
        int s = i / 96, o = i % 96;
        float a = 0.f;
        for (int c = 0; c < 160; c++)
            a += sIn[s][c] * __ldg(Wu0 + (size_t)c * 96 + o);
        sMid[s][o] = fmaxf(a, 0.f);
    }
    __syncthreads();

    for (int i = tid; i < BSEED * 512; i += 256) {
        int s = i / 512, o = i % 512;
        float a = 0.f;
        for (int c = 0; c < 96; c++)
            a += sMid[s][c] * __ldg(Wout + (size_t)c * 512 + o);
        int g = g0 + s;
        int b = g / PS, si = g % PS;
        out[(size_t)b * 512 * PS + (size_t)o * PS + si] = a;
    }
}

// ---------------- launch ----------------
extern "C" void kernel_launch(void* const* d_in, const int* in_sizes, int n_in,
                              void* d_out, int out_size)
{
    (void)in_sizes; (void)n_in; (void)out_size;
    const float* feats   = (const float*)d_in[0];
    const int*   nbr0    = (const int*)d_in[1];
    const int*   nbr1    = (const int*)d_in[2];
    const int*   nbr2    = (const int*)d_in[3];
    const int*   nbr3    = (const int*)d_in[4];
    const int*   down1   = (const int*)d_in[5];
    const int*   down2   = (const int*)d_in[6];
    const int*   down3   = (const int*)d_in[7];
    const int*   up2     = (const int*)d_in[8];
    const int*   up1     = (const int*)d_in[9];
    const int*   up0     = (const int*)d_in[10];
    const int*   seedidx = (const int*)d_in[11];
    const float* W_stem  = (const float*)d_in[12];
    const float* W_b0    = (const float*)d_in[13];
    const float* W_d1    = (const float*)d_in[14];
    const float* W_b1    = (const float*)d_in[15];
    const float* W_d2    = (const float*)d_in[16];
    const float* W_b2    = (const float*)d_in[17];
    const float* W_d3    = (const float*)d_in[18];
    const float* W_b3    = (const float*)d_in[19];
    const float* W_u2    = (const float*)d_in[20];
    const float* W_u1    = (const float*)d_in[21];
    const float* W_u0    = (const float*)d_in[22];
    const float* W_out   = (const float*)d_in[23];

    float *px0, *pt0, *px1, *pt1, *px2, *pt2, *px3, *pt3;
    cudaGetSymbolAddress((void**)&px0, g_x0);
    cudaGetSymbolAddress((void**)&pt0, g_t0);
    cudaGetSymbolAddress((void**)&px1, g_x1);
    cudaGetSymbolAddress((void**)&pt1, g_t1);
    cudaGetSymbolAddress((void**)&px2, g_x2);
    cudaGetSymbolAddress((void**)&pt2, g_t2);
    cudaGetSymbolAddress((void**)&px3, g_x3);
    cudaGetSymbolAddress((void**)&pt3, g_t3);

    float *wb0, *wd1, *wb1, *wd2, *wb2, *wd3, *wb3;
    cudaGetSymbolAddress((void**)&wb0, g_wb0);
    cudaGetSymbolAddress((void**)&wd1, g_wd1);
    cudaGetSymbolAddress((void**)&wb1, g_wb1);
    cudaGetSymbolAddress((void**)&wd2, g_wd2);
    cudaGetSymbolAddress((void**)&wb2, g_wb2);
    cudaGetSymbolAddress((void**)&wd3, g_wd3);
    cudaGetSymbolAddress((void**)&wb3, g_wb3);

    constexpr int sm_b0 = mma_smem_bytes(32, 32);
    constexpr int sm_d1 = mma_smem_bytes(32, 64);
    constexpr int sm_b1 = mma_smem_bytes(64, 64);
    constexpr int sm_hi = mma_smem_bytes(128, 128);   // d2/b2/d3/b3 (CC=64, NT=128)

    cudaFuncSetAttribute((const void*)spconv_mma<27, 32, 32, 32, true, true>,
                         cudaFuncAttributeMaxDynamicSharedMemorySize, sm_b0);
    cudaFuncSetAttribute((const void*)spconv_mma<8, 32, 64, 64, false, true>,
                         cudaFuncAttributeMaxDynamicSharedMemorySize, sm_d1);
    cudaFuncSetAttribute((const void*)spconv_mma<27, 64, 64, 64, true, true>,
                         cudaFuncAttributeMaxDynamicSharedMemorySize, sm_b1);
    cudaFuncSetAttribute((const void*)spconv_mma<8, 64, 128, 128, false, true>,
                         cudaFuncAttributeMaxDynamicSharedMemorySize, sm_hi);
    cudaFuncSetAttribute((const void*)spconv_mma<27, 128, 128, 128, true, true>,
                         cudaFuncAttributeMaxDynamicSharedMemorySize, sm_hi);
    cudaFuncSetAttribute((const void*)spconv_mma<8, 128, 256, 128, false, true>,
                         cudaFuncAttributeMaxDynamicSharedMemorySize, sm_hi);
    cudaFuncSetAttribute((const void*)spconv_mma<27, 256, 256, 128, true, false>,
                         cudaFuncAttributeMaxDynamicSharedMemorySize, sm_hi);

    // ---- pre-convert conv weights to tf32 (raw cp.async staging later) ----
    auto cvt = [](const float* s, float* d, int n) {
        cvt_tf32_kernel<<<(n + 255) / 256, 256>>>(s, d, n);
    };
    cvt(W_b0, wb0, 27 * 32 * 32);
    cvt(W_d1, wd1, 8 * 32 * 64);
    cvt(W_b1, wb1, 27 * 64 * 64);
    cvt(W_d2, wd2, 8 * 64 * 128);
    cvt(W_b2, wb2, 27 * 128 * 128);
    cvt(W_d3, wd3, 8 * 128 * 256);
    cvt(W_b3, wb3, 27 * 256 * 256);

    const int gm0 = (PN0 + 127) / 128;
    const int gm1 = (PN1 + 127) / 128;
    const int gm2 = (PN2 + 127) / 128;
    const int gm3 = (PN3 + 127) / 128;

    // stem: scalar fp32, output tf32-rounded
    spconv_stem<27, 3, C0><<<(PN0 + 31) / 32, 256>>>(feats, nbr0, W_stem, px0, PN0);

    // encoder: tensor-core tf32 gather-GEMMs with cp.async pipeline
    spconv_mma<27, 32, 32, 32, true, true><<<dim3(gm0, 1), 256, sm_b0>>>(
        px0, nbr0, wb0, px0, pt0, PN0);
    spconv_mma<8, 32, 64, 64, false, true><<<dim3(gm1, 1), 256, sm_d1>>>(
        pt0, down1, wd1, nullptr, px1, PN1);
    spconv_mma<27, 64, 64, 64, true, true><<<dim3(gm1, 1), 256, sm_b1>>>(
        px1, nbr1, wb1, px1, pt1, PN1);
    spconv_mma<8, 64, 128, 128, false, true><<<dim3(gm2, 1), 256, sm_hi>>>(
        pt1, down2, wd2, nullptr, px2, PN2);
    spconv_mma<27, 128, 128, 128, true, true><<<dim3(gm2, 1), 256, sm_hi>>>(
        px2, nbr2, wb2, px2, pt2, PN2);
    spconv_mma<8, 128, 256, 128, false, true><<<dim3(gm3, 2), 256, sm_hi>>>(
        pt2, down3, wd3, nullptr, px3, PN3);
    spconv_mma<27, 256, 256, 128, true, false><<<dim3(gm3, 2), 256, sm_hi>>>(
        px3, nbr3, wb3, px3, pt3, PN3);

    // fused sparse decoder over seed chains only
    decoder_kernel<<<(PB * PS) / BSEED, 256>>>(
        pt0, pt1, pt2, pt3, up0, up1, up2, seedidx,
        W_u2, W_u1, W_u0, W_out, (float*)d_out);
}

// round 11
// speedup vs baseline: 5.0466x; 1.6545x over previous
#include <cuda_runtime.h>
#include <cuda_fp16.h>
#include <cstdint>

// ---------------- problem constants ----------------
#define PN0 100000
#define PN1 50000
#define PN2 25000
#define PN3 12500
#define PB  8
#define PS  1024
#define C0 32
#define C1 64
#define C2 128
#define C3 256

// ---------------- scratch (device globals; no allocation allowed) ----------------
// fp16 activations; __align__(256) because cp.async.16 needs 16B-aligned src.
__device__ __align__(256) __half g_x0[PN0 * C0];
__device__ __align__(256) __half g_t0[PN0 * C0];
__device__ __align__(256) __half g_x1[PN1 * C1];
__device__ __align__(256) __half g_t1[PN1 * C1];
__device__ __align__(256) __half g_x2[PN2 * C2];
__device__ __align__(256) __half g_t2[PN2 * C2];
__device__ __align__(256) __half g_x3[PN3 * C3];
__device__ __align__(256) __half g_t3[PN3 * C3];

// fp16 weights, TRANSPOSED to [k][o][c] so B tiles stage row-per-output
__device__ __align__(256) __half g_wb0[27 * 32 * 32];
__device__ __align__(256) __half g_wd1[8 * 32 * 64];
__device__ __align__(256) __half g_wb1[27 * 64 * 64];
__device__ __align__(256) __half g_wd2[8 * 64 * 128];
__device__ __align__(256) __half g_wb2[27 * 128 * 128];
__device__ __align__(256) __half g_wd3[8 * 128 * 256];
__device__ __align__(256) __half g_wb3[27 * 256 * 256];

// ---------------- helpers ----------------
__device__ __forceinline__ void mma_f16(float d[4], const uint32_t a[4],
                                        uint32_t b0, uint32_t b1) {
    asm volatile(
        "mma.sync.aligned.m16n8k16.row.col.f32.f16.f16.f32 "
        "{%0,%1,%2,%3}, {%4,%5,%6,%7}, {%8,%9}, {%0,%1,%2,%3};\n"
        : "+f"(d[0]), "+f"(d[1]), "+f"(d[2]), "+f"(d[3])
        : "r"(a[0]), "r"(a[1]), "r"(a[2]), "r"(a[3]), "r"(b0), "r"(b1));
}

__device__ __forceinline__ void cp_async16(void* dst_smem, const void* src) {
    uint32_t d = (uint32_t)__cvta_generic_to_shared(dst_smem);
    asm volatile("cp.async.cg.shared.global [%0], [%1], 16;" :: "r"(d), "l"(src));
}
__device__ __forceinline__ void cp_commit() {
    asm volatile("cp.async.commit_group;");
}
template <int NN>
__device__ __forceinline__ void cp_wait() {
    asm volatile("cp.async.wait_group %0;" :: "n"(NN));
}

// ---------------- weight conversion: fp32 [k][c][o] -> fp16 [k][o][c] ----------------
__global__ void cvt_f16_t_kernel(const float* __restrict__ src,
                                 __half* __restrict__ dst,
                                 int Cin, int Cout, int total) {
    int i = blockIdx.x * 256 + threadIdx.x;
    if (i < total) {
        int kco = Cin * Cout;
        int k = i / kco, rem = i % kco;
        int c = rem / Cout, o = rem % Cout;
        dst[(size_t)k * kco + (size_t)o * Cin + c] = __float2half_rn(src[i]);
    }
}

// ---------------- tensor-core implicit gather-GEMM sparse conv (fp16 mma) ----------------
// out[n,o] = (resid?) + relu( sum_k sum_c f[nbr[n,k],c] * W[k,c,o] )
// A: [128][CC] gathered rows. B: [NT][CC] transposed weight tile.
// Double-buffered cp.async pipeline; fragments via direct 32-bit smem loads
// (layout identical in structure to the validated tf32 path).
template <int KK, int CIN, int COUT, int NT, bool RESID>
__global__ __launch_bounds__(256) void spconv_mma(
    const __half* __restrict__ f, const int* __restrict__ nbr,
    const __half* __restrict__ Wt, const __half* __restrict__ resid,
    __half* __restrict__ out, int N)
{
    constexpr int WM = (NT == 32) ? 8 : 4;
    constexpr int WN = 8 / WM;
    constexpr int WTM = 128 / WM;
    constexpr int WTN = NT / WN;
    constexpr int MF = WTM / 16;
    constexpr int NF = WTN / 8;
    constexpr int CC  = (CIN < 64) ? CIN : 64;  // k-chunk (halves)
    constexpr int NCH = CIN / CC;
    constexpr int NSTAGE = KK * NCH;
    constexpr int AP = CC + 8;     // pitch in halves; (CC+8)*2 bytes % 16 == 0
    constexpr int BP = CC + 8;     // B transposed tile pitch
    constexpr int A8 = CC / 8;     // 16B segments per row

    extern __shared__ __half smemh[];
    __half* sA0 = smemh;                    // [2][128][AP]
    __half* sB0 = smemh + 2 * 128 * AP;     // [2][NT][BP]

    const int tid  = threadIdx.x;
    const int warp = tid >> 5;
    const int lane = tid & 31;
    const int gId  = lane >> 2;   // 0..7
    const int tig  = lane & 3;    // 0..3
    const int wm = warp % WM;
    const int wn = warp / WM;
    const int n0  = blockIdx.x * 128;
    const int nt0 = blockIdx.y * NT;

    // ---- stage issue: gather A chunk + copy transposed B chunk ----
    auto stage = [&](int buf, int s) {
        const int k = s / NCH, ch = s % NCH;
        __half* dA = sA0 + buf * 128 * AP;
        __half* dB = sB0 + buf * NT * BP;
#pragma unroll
        for (int i = tid; i < 128 * A8; i += 256) {
            int row = i / A8, c8 = i % A8;
            int n = n0 + row;
            int idx = (n < N) ? __ldg(nbr + (size_t)n * KK + k) : 0;
            cp_async16(dA + row * AP + c8 * 8,
                       f + (size_t)idx * CIN + ch * CC + c8 * 8);
        }
        // Wt layout: [k][o][c]; tile rows o in [nt0, nt0+NT), cols c in [ch*CC, +CC)
        const __half* WkT = Wt + (size_t)k * CIN * COUT + (size_t)nt0 * CIN + ch * CC;
#pragma unroll
        for (int i = tid; i < NT * A8; i += 256) {
            int r = i / A8, c8 = i % A8;
            cp_async16(dB + r * BP + c8 * 8, WkT + (size_t)r * CIN + c8 * 8);
        }
        cp_commit();
    };

    float acc[MF][NF][4];
#pragma unroll
    for (int mf = 0; mf < MF; mf++)
#pragma unroll
        for (int nf = 0; nf < NF; nf++)
#pragma unroll
            for (int i = 0; i < 4; i++) acc[mf][nf][i] = 0.f;

    stage(0, 0);

    for (int s = 0; s < NSTAGE; s++) {
        const int buf = s & 1;
        if (s + 1 < NSTAGE) {
            stage(buf ^ 1, s + 1);
            cp_wait<1>();
        } else {
            cp_wait<0>();
        }
        __syncthreads();

        const __half* A = sA0 + buf * 128 * AP;
        const __half* B = sB0 + buf * NT * BP;
#pragma unroll
        for (int k16 = 0; k16 < CC / 16; k16++) {
            const int k0 = k16 * 16;
            uint32_t a[MF][4];
#pragma unroll
            for (int mf = 0; mf < MF; mf++) {
                // A frag: a0=(g,2t..2t+1) a1=(g+8,..) a2=(g,2t+8..) a3=(g+8,2t+8..)
                const __half* ap = A + (wm * WTM + mf * 16 + gId) * AP + k0 + 2 * tig;
                a[mf][0] = *(const uint32_t*)(ap);
                a[mf][1] = *(const uint32_t*)(ap + 8 * AP);
                a[mf][2] = *(const uint32_t*)(ap + 8);
                a[mf][3] = *(const uint32_t*)(ap + 8 * AP + 8);
            }
#pragma unroll
            for (int nf = 0; nf < NF; nf++) {
                // B frag from transposed tile: b0=(n=g, k=2t..2t+1) b1=(n=g, k=2t+8..)
                const __half* bp = B + (wn * WTN + nf * 8 + gId) * BP + k0 + 2 * tig;
                uint32_t b0 = *(const uint32_t*)(bp);
                uint32_t b1 = *(const uint32_t*)(bp + 8);
#pragma unroll
                for (int mf = 0; mf < MF; mf++)
                    mma_f16(acc[mf][nf], a[mf], b0, b1);
            }
        }
        __syncthreads();
    }

    // ---- epilogue: relu (+ residual), half2 stores (C-frag layout as validated) ----
#pragma unroll
    for (int mf = 0; mf < MF; mf++) {
        const int r = wm * WTM + mf * 16 + gId;
#pragma unroll
        for (int nf = 0; nf < NF; nf++) {
            const int o = nt0 + wn * WTN + nf * 8 + 2 * tig;
            int n = n0 + r;
            if (n < N) {
                float vx = fmaxf(acc[mf][nf][0], 0.f);
                float vy = fmaxf(acc[mf][nf][1], 0.f);
                if constexpr (RESID) {
                    __half2 rr = *(const __half2*)(resid + (size_t)n * COUT + o);
                    vx += __half2float(__low2half(rr));
                    vy += __half2float(__high2half(rr));
                }
                *(__half2*)(out + (size_t)n * COUT + o) = __floats2half2_rn(vx, vy);
            }
            int n2 = n0 + r + 8;
            if (n2 < N) {
                float vx = fmaxf(acc[mf][nf][2], 0.f);
                float vy = fmaxf(acc[mf][nf][3], 0.f);
                if constexpr (RESID) {
                    __half2 rr = *(const __half2*)(resid + (size_t)n2 * COUT + o);
                    vx += __half2float(__low2half(rr));
                    vy += __half2float(__high2half(rr));
                }
                *(__half2*)(out + (size_t)n2 * COUT + o) = __floats2half2_rn(vx, vy);
            }
        }
    }
}

constexpr int mma_smem_bytes(int CIN, int NT) {
    int cc = (CIN < 64) ? CIN : 64;
    return (2 * 128 * (cc + 8) + 2 * NT * (cc + 8)) * 2;
}

// ---------------- scalar fp32 conv for the stem (CIN=3), fp16 output ----------------
template <int KK, int CIN, int COUT>
__global__ __launch_bounds__(256) void spconv_stem(
    const float* __restrict__ f, const int* __restrict__ nbr,
    const float* __restrict__ W, __half* __restrict__ out, int N)
{
    constexpr int M_TILE = 32;
    constexpr int OREP = 256 / COUT;
    constexpr int MT   = M_TILE / OREP;

    __shared__ __align__(16) float As[M_TILE][CIN];
    __shared__ int s_idx[M_TILE * KK];

    const int tid = threadIdx.x;
    const int n0  = blockIdx.x * M_TILE;
    const int o   = tid % COUT;
    const int mg  = tid / COUT;

    for (int i = tid; i < M_TILE * KK; i += 256) {
        int n = n0 + i / KK;
        s_idx[i] = (n < N) ? nbr[(size_t)n0 * KK + i] : 0;
    }

    float acc[MT];
#pragma unroll
    for (int mi = 0; mi < MT; mi++) acc[mi] = 0.f;

    for (int k = 0; k < KK; k++) {
        __syncthreads();
        for (int i = tid; i < M_TILE * CIN; i += 256) {
            int m = i / CIN, c = i % CIN;
            As[m][c] = __ldg(f + (size_t)s_idx[m * KK + k] * CIN + c);
        }
        __syncthreads();
        const float* Wk = W + (size_t)k * CIN * COUT;
        for (int c = 0; c < CIN; c++) {
            float w = __ldg(Wk + (size_t)c * COUT + o);
#pragma unroll
            for (int mi = 0; mi < MT; mi++)
                acc[mi] += As[mg * MT + mi][c] * w;
        }
    }

#pragma unroll
    for (int mi = 0; mi < MT; mi++) {
        int n = n0 + mg * MT + mi;
        if (n < N)
            out[(size_t)n * COUT + o] = __float2half_rn(fmaxf(acc[mi], 0.f));
    }
}

// ---------------- fused sparse decoder over seed chains (fp32 math, fp16 activations) ----------------
#define BSEED 4
__global__ __launch_bounds__(256) void decoder_kernel(
    const __half* __restrict__ x0, const __half* __restrict__ x1,
    const __half* __restrict__ x2, const __half* __restrict__ x3,
    const int* __restrict__ up0, const int* __restrict__ up1,
    const int* __restrict__ up2, const int* __restrict__ seed_idx,
    const float* __restrict__ Wu2, const float* __restrict__ Wu1,
    const float* __restrict__ Wu0, const float* __restrict__ Wout,
    float* __restrict__ out)
{
    __shared__ float sIn[BSEED][384];
    __shared__ float sMid[BSEED][256];
    __shared__ int sP[BSEED], sJ1[BSEED], sJ2[BSEED], sJ3[BSEED];

    const int tid = threadIdx.x;
    const int g0  = blockIdx.x * BSEED;

    if (tid < BSEED) {
        int p  = seed_idx[g0 + tid];
        int j1 = up0[p];
        int j2 = up1[j1];
        int j3 = up2[j2];
        sP[tid] = p; sJ1[tid] = j1; sJ2[tid] = j2; sJ3[tid] = j3;
    }
    __syncthreads();

    for (int i = tid; i < BSEED * 384; i += 256) {
        int s = i / 384, c = i % 384;
        sIn[s][c] = (c < 256) ? __half2float(x3[(size_t)sJ3[s] * 256 + c])
                              : __half2float(x2[(size_t)sJ2[s] * 128 + (c - 256)]);
    }
    __syncthreads();

    {
        float a0 = 0.f, a1 = 0.f, a2 = 0.f, a3 = 0.f;
        const int o = tid;
        for (int c = 0; c < 384; c++) {
            float w = __ldg(Wu2 + (size_t)c * 256 + o);
            a0 += sIn[0][c] * w; a1 += sIn[1][c] * w;
            a2 += sIn[2][c] * w; a3 += sIn[3][c] * w;
        }
        sMid[0][o] = fmaxf(a0, 0.f); sMid[1][o] = fmaxf(a1, 0.f);
        sMid[2][o] = fmaxf(a2, 0.f); sMid[3][o] = fmaxf(a3, 0.f);
    }
    __syncthreads();

    for (int i = tid; i < BSEED * 320; i += 256) {
        int s = i / 320, c = i % 320;
        sIn[s][c] = (c < 256) ? sMid[s][c]
                              : __half2float(x1[(size_t)sJ1[s] * 64 + (c - 256)]);
    }
    __syncthreads();

    {
        const int o  = tid % 128;
        const int sh = tid / 128;
        float a0 = 0.f, a1 = 0.f;
        for (int c = 0; c < 320; c++) {
            float w = __ldg(Wu1 + (size_t)c * 128 + o);
            a0 += sIn[sh][c] * w;
            a1 += sIn[sh + 2][c] * w;
        }
        __syncthreads();
        sMid[sh][o]     = fmaxf(a0, 0.f);
        sMid[sh + 2][o] = fmaxf(a1, 0.f);
    }
    __syncthreads();

    for (int i = tid; i < BSEED * 160; i += 256) {
        int s = i / 160, c = i % 160;
        sIn[s][c] = (c < 128) ? sMid[s][c]
                              : __half2float(x0[(size_t)sP[s] * 32 + (c - 128)]);
    }
    __syncthreads();

    for (int i = tid; i < BSEED * 96; i += 256) {
        int s = i / 96, o = i % 96;
        float a = 0.f;
        for (int c = 0; c < 160; c++)
            a += sIn[s][c] * __ldg(Wu0 + (size_t)c * 96 + o);
        sMid[s][o] = fmaxf(a, 0.f);
    }
    __syncthreads();

    for (int i = tid; i < BSEED * 512; i += 256) {
        int s = i / 512, o = i % 512;
        float a = 0.f;
        for (int c = 0; c < 96; c++)
            a += sMid[s][c] * __ldg(Wout + (size_t)c * 512 + o);
        int g = g0 + s;
        int b = g / PS, si = g % PS;
        out[(size_t)b * 512 * PS + (size_t)o * PS + si] = a;
    }
}

// ---------------- launch ----------------
extern "C" void kernel_launch(void* const* d_in, const int* in_sizes, int n_in,
                              void* d_out, int out_size)
{
    (void)in_sizes; (void)n_in; (void)out_size;
    const float* feats   = (const float*)d_in[0];
    const int*   nbr0    = (const int*)d_in[1];
    const int*   nbr1    = (const int*)d_in[2];
    const int*   nbr2    = (const int*)d_in[3];
    const int*   nbr3    = (const int*)d_in[4];
    const int*   down1   = (const int*)d_in[5];
    const int*   down2   = (const int*)d_in[6];
    const int*   down3   = (const int*)d_in[7];
    const int*   up2     = (const int*)d_in[8];
    const int*   up1     = (const int*)d_in[9];
    const int*   up0     = (const int*)d_in[10];
    const int*   seedidx = (const int*)d_in[11];
    const float* W_stem  = (const float*)d_in[12];
    const float* W_b0    = (const float*)d_in[13];
    const float* W_d1    = (const float*)d_in[14];
    const float* W_b1    = (const float*)d_in[15];
    const float* W_d2    = (const float*)d_in[16];
    const float* W_b2    = (const float*)d_in[17];
    const float* W_d3    = (const float*)d_in[18];
    const float* W_b3    = (const float*)d_in[19];
    const float* W_u2    = (const float*)d_in[20];
    const float* W_u1    = (const float*)d_in[21];
    const float* W_u0    = (const float*)d_in[22];
    const float* W_out   = (const float*)d_in[23];

    __half *px0, *pt0, *px1, *pt1, *px2, *pt2, *px3, *pt3;
    cudaGetSymbolAddress((void**)&px0, g_x0);
    cudaGetSymbolAddress((void**)&pt0, g_t0);
    cudaGetSymbolAddress((void**)&px1, g_x1);
    cudaGetSymbolAddress((void**)&pt1, g_t1);
    cudaGetSymbolAddress((void**)&px2, g_x2);
    cudaGetSymbolAddress((void**)&pt2, g_t2);
    cudaGetSymbolAddress((void**)&px3, g_x3);
    cudaGetSymbolAddress((void**)&pt3, g_t3);

    __half *wb0, *wd1, *wb1, *wd2, *wb2, *wd3, *wb3;
    cudaGetSymbolAddress((void**)&wb0, g_wb0);
    cudaGetSymbolAddress((void**)&wd1, g_wd1);
    cudaGetSymbolAddress((void**)&wb1, g_wb1);
    cudaGetSymbolAddress((void**)&wd2, g_wd2);
    cudaGetSymbolAddress((void**)&wb2, g_wb2);
    cudaGetSymbolAddress((void**)&wd3, g_wd3);
    cudaGetSymbolAddress((void**)&wb3, g_wb3);

    constexpr int sm_b0 = mma_smem_bytes(32, 32);
    constexpr int sm_d1 = mma_smem_bytes(32, 64);
    constexpr int sm_b1 = mma_smem_bytes(64, 64);
    constexpr int sm_hi = mma_smem_bytes(128, 128);

    cudaFuncSetAttribute((const void*)spconv_mma<27, 32, 32, 32, true>,
                         cudaFuncAttributeMaxDynamicSharedMemorySize, sm_b0);
    cudaFuncSetAttribute((const void*)spconv_mma<8, 32, 64, 64, false>,
                         cudaFuncAttributeMaxDynamicSharedMemorySize, sm_d1);
    cudaFuncSetAttribute((const void*)spconv_mma<27, 64, 64, 64, true>,
                         cudaFuncAttributeMaxDynamicSharedMemorySize, sm_b1);
    cudaFuncSetAttribute((const void*)spconv_mma<8, 64, 128, 128, false>,
                         cudaFuncAttributeMaxDynamicSharedMemorySize, sm_hi);
    cudaFuncSetAttribute((const void*)spconv_mma<27, 128, 128, 128, true>,
                         cudaFuncAttributeMaxDynamicSharedMemorySize, sm_hi);
    cudaFuncSetAttribute((const void*)spconv_mma<8, 128, 256, 128, false>,
                         cudaFuncAttributeMaxDynamicSharedMemorySize, sm_hi);
    cudaFuncSetAttribute((const void*)spconv_mma<27, 256, 256, 128, true>,
                         cudaFuncAttributeMaxDynamicSharedMemorySize, sm_hi);

    // ---- pre-convert conv weights to fp16, transposed to [k][o][c] ----
    auto cvt = [](const float* s, __half* d, int K_, int Cin, int Cout) {
        int n = K_ * Cin * Cout;
        cvt_f16_t_kernel<<<(n + 255) / 256, 256>>>(s, d, Cin, Cout, n);
    };
    cvt(W_b0, wb0, 27, 32, 32);
    cvt(W_d1, wd1, 8, 32, 64);
    cvt(W_b1, wb1, 27, 64, 64);
    cvt(W_d2, wd2, 8, 64, 128);
    cvt(W_b2, wb2, 27, 128, 128);
    cvt(W_d3, wd3, 8, 128, 256);
    cvt(W_b3, wb3, 27, 256, 256);

    const int gm0 = (PN0 + 127) / 128;
    const int gm1 = (PN1 + 127) / 128;
    const int gm2 = (PN2 + 127) / 128;
    const int gm3 = (PN3 + 127) / 128;

    // stem: scalar fp32, fp16 output
    spconv_stem<27, 3, C0><<<(PN0 + 31) / 32, 256>>>(feats, nbr0, W_stem, px0, PN0);

    // encoder: fp16 tensor-core gather-GEMMs with cp.async pipeline
    spconv_mma<27, 32, 32, 32, true><<<dim3(gm0, 1), 256, sm_b0>>>(
        px0, nbr0, wb0, px0, pt0, PN0);
    spconv_mma<8, 32, 64, 64, false><<<dim3(gm1, 1), 256, sm_d1>>>(
        pt0, down1, wd1, nullptr, px1, PN1);
    spconv_mma<27, 64, 64, 64, true><<<dim3(gm1, 1), 256, sm_b1>>>(
        px1, nbr1, wb1, px1, pt1, PN1);
    spconv_mma<8, 64, 128, 128, false><<<dim3(gm2, 1), 256, sm_hi>>>(
        pt1, down2, wd2, nullptr, px2, PN2);
    spconv_mma<27, 128, 128, 128, true><<<dim3(gm2, 1), 256, sm_hi>>>(
        px2, nbr2, wb2, px2, pt2, PN2);
    spconv_mma<8, 128, 256, 128, false><<<dim3(gm3, 2), 256, sm_hi>>>(
        pt2, down3, wd3, nullptr, px3, PN3);
    spconv_mma<27, 256, 256, 128, true><<<dim3(gm3, 2), 256, sm_hi>>>(
        px3, nbr3, wb3, px3, pt3, PN3);

    // fused sparse decoder over seed chains only
    decoder_kernel<<<(PB * PS) / BSEED, 256>>>(
        pt0, pt1, pt2, pt3, up0, up1, up2, seedidx,
        W_u2, W_u1, W_u0, W_out, (float*)d_out);
}

// round 16
// speedup vs baseline: 6.9837x; 1.3838x over previous
#include <cuda_runtime.h>
#include <cuda_fp16.h>
#include <cstdint>

// ---------------- problem constants ----------------
#define PN0 100000
#define PN1 50000
#define PN2 25000
#define PN3 12500
#define PB  8
#define PS  1024
#define NSEED (PB * PS)
#define C0 32
#define C1 64
#define C2 128
#define C3 256

// ---------------- scratch (device globals; no allocation allowed) ----------------
__device__ __align__(256) __half g_x0[PN0 * C0];
__device__ __align__(256) __half g_t0[PN0 * C0];
__device__ __align__(256) __half g_x1[PN1 * C1];
__device__ __align__(256) __half g_t1[PN1 * C1];
__device__ __align__(256) __half g_x2[PN2 * C2];
__device__ __align__(256) __half g_t2[PN2 * C2];
__device__ __align__(256) __half g_x3[PN3 * C3];
__device__ __align__(256) __half g_t3[PN3 * C3];

// fp16 conv weights transposed to [k][o][c]
__device__ __align__(256) __half g_wb0[27 * 32 * 32];
__device__ __align__(256) __half g_wd1[8 * 32 * 64];
__device__ __align__(256) __half g_wb1[27 * 64 * 64];
__device__ __align__(256) __half g_wd2[8 * 64 * 128];
__device__ __align__(256) __half g_wb2[27 * 128 * 128];
__device__ __align__(256) __half g_wd3[8 * 128 * 256];
__device__ __align__(256) __half g_wb3[27 * 256 * 256];

// fp16 decoder weights transposed to [o][c]
__device__ __align__(256) __half g_wu2[256 * 384];
__device__ __align__(256) __half g_wu1[128 * 320];
__device__ __align__(256) __half g_wu0[96 * 160];
__device__ __align__(256) __half g_wo[512 * 96];

// decoder seed-chain indices and intermediates
__device__ int g_chp[NSEED];
__device__ int g_ch1[NSEED];
__device__ int g_ch2[NSEED];
__device__ int g_ch3[NSEED];
__device__ __align__(256) __half g_ut2[NSEED * 256];
__device__ __align__(256) __half g_u2[NSEED * 256];
__device__ __align__(256) __half g_ut1[NSEED * 128];
__device__ __align__(256) __half g_u1[NSEED * 128];
__device__ __align__(256) __half g_ut0[NSEED * 96];
__device__ __align__(256) __half g_u0[NSEED * 96];

// ---------------- helpers ----------------
__device__ __forceinline__ void mma_f16(float d[4], const uint32_t a[4],
                                        uint32_t b0, uint32_t b1) {
    asm volatile(
        "mma.sync.aligned.m16n8k16.row.col.f32.f16.f16.f32 "
        "{%0,%1,%2,%3}, {%4,%5,%6,%7}, {%8,%9}, {%0,%1,%2,%3};\n"
        : "+f"(d[0]), "+f"(d[1]), "+f"(d[2]), "+f"(d[3])
        : "r"(a[0]), "r"(a[1]), "r"(a[2]), "r"(a[3]), "r"(b0), "r"(b1));
}
__device__ __forceinline__ void cp_async16(void* dst_smem, const void* src) {
    uint32_t d = (uint32_t)__cvta_generic_to_shared(dst_smem);
    asm volatile("cp.async.cg.shared.global [%0], [%1], 16;" :: "r"(d), "l"(src));
}
__device__ __forceinline__ void cp_commit() {
    asm volatile("cp.async.commit_group;");
}
template <int NN>
__device__ __forceinline__ void cp_wait() {
    asm volatile("cp.async.wait_group %0;" :: "n"(NN));
}

__host__ __device__ constexpr int cc_of(int cin) {
    return cin % 64 == 0 ? 64 : (cin == 96 ? 48 : cin);
}
__host__ __device__ constexpr int smem_g(int CIN, int NT) {
    return (2 * 128 * (cc_of(CIN) + 8) + 2 * NT * (cc_of(CIN) + 8)) * 2;
}

// ---------------- generalized fp16 gather-GEMM ----------------
// out[n,o] = epi( sum_k sum_c f[idx(n,k),c] * W[k][o][c] )
// IDX: 0 = nbr[n*KK+k], 1 = chain nbr[n], 2 = identity
// EPI: 0 = relu; 1 = relu then +resid (encoder residual block);
//      2 = +resid then relu (concat split); 3 = linear fp16;
//      4 = linear fp32 transposed store to fout[b][o][si]
template <int KK, int CIN, int COUT, int NT, int IDX, int EPI>
__global__ __launch_bounds__(256) void spconv_g(
    const __half* __restrict__ f, const int* __restrict__ nbr,
    const __half* __restrict__ Wt, int wpitch,
    const __half* __restrict__ resid,
    __half* __restrict__ out, float* __restrict__ fout, int N)
{
    constexpr int WM = (NT == 32) ? 8 : 4;
    constexpr int WN = 8 / WM;
    constexpr int WTM = 128 / WM;
    constexpr int WTN = NT / WN;
    constexpr int MF = WTM / 16;
    constexpr int NF = WTN / 8;
    constexpr int CC  = cc_of(CIN);
    constexpr int NCH = CIN / CC;
    constexpr int NSTAGE = KK * NCH;
    constexpr int AP = CC + 8;
    constexpr int BP = CC + 8;
    constexpr int A8 = CC / 8;

    extern __shared__ __half smemh[];
    __half* sA0 = smemh;                    // [2][128][AP]
    __half* sB0 = smemh + 2 * 128 * AP;     // [2][NT][BP]

    const int tid  = threadIdx.x;
    const int warp = tid >> 5;
    const int lane = tid & 31;
    const int gId  = lane >> 2;
    const int tig  = lane & 3;
    const int wm = warp % WM;
    const int wn = warp / WM;
    const int n0  = blockIdx.x * 128;
    const int nt0 = blockIdx.y * NT;

    auto stage = [&](int buf, int s) {
        const int k = s / NCH, ch = s % NCH;
        __half* dA = sA0 + buf * 128 * AP;
        __half* dB = sB0 + buf * NT * BP;
#pragma unroll
        for (int i = tid; i < 128 * A8; i += 256) {
            int row = i / A8, c8 = i % A8;
            int n = n0 + row;
            int idx;
            if constexpr (IDX == 0)      idx = (n < N) ? __ldg(nbr + (size_t)n * KK + k) : 0;
            else if constexpr (IDX == 1) idx = (n < N) ? __ldg(nbr + n) : 0;
            else                         idx = (n < N) ? n : 0;
            cp_async16(dA + row * AP + c8 * 8,
                       f + (size_t)idx * CIN + ch * CC + c8 * 8);
        }
        const __half* WkT = Wt + ((size_t)k * COUT + nt0) * wpitch + ch * CC;
#pragma unroll
        for (int i = tid; i < NT * A8; i += 256) {
            int r = i / A8, c8 = i % A8;
            cp_async16(dB + r * BP + c8 * 8, WkT + (size_t)r * wpitch + c8 * 8);
        }
        cp_commit();
    };

    float acc[MF][NF][4];
#pragma unroll
    for (int mf = 0; mf < MF; mf++)
#pragma unroll
        for (int nf = 0; nf < NF; nf++)
#pragma unroll
            for (int i = 0; i < 4; i++) acc[mf][nf][i] = 0.f;

    stage(0, 0);

    for (int s = 0; s < NSTAGE; s++) {
        const int buf = s & 1;
        if (s + 1 < NSTAGE) {
            stage(buf ^ 1, s + 1);
            cp_wait<1>();
        } else {
            cp_wait<0>();
        }
        __syncthreads();

        const __half* A = sA0 + buf * 128 * AP;
        const __half* B = sB0 + buf * NT * BP;
#pragma unroll
        for (int k16 = 0; k16 < CC / 16; k16++) {
            const int k0 = k16 * 16;
            uint32_t a[MF][4];
#pragma unroll
            for (int mf = 0; mf < MF; mf++) {
                const __half* ap = A + (wm * WTM + mf * 16 + gId) * AP + k0 + 2 * tig;
                a[mf][0] = *(const uint32_t*)(ap);
                a[mf][1] = *(const uint32_t*)(ap + 8 * AP);
                a[mf][2] = *(const uint32_t*)(ap + 8);
                a[mf][3] = *(const uint32_t*)(ap + 8 * AP + 8);
            }
#pragma unroll
            for (int nf = 0; nf < NF; nf++) {
                const __half* bp = B + (wn * WTN + nf * 8 + gId) * BP + k0 + 2 * tig;
                uint32_t b0 = *(const uint32_t*)(bp);
                uint32_t b1 = *(const uint32_t*)(bp + 8);
#pragma unroll
                for (int mf = 0; mf < MF; mf++)
                    mma_f16(acc[mf][nf], a[mf], b0, b1);
            }
        }
        __syncthreads();
    }

    // ---- epilogue ----
    auto emit = [&](int n, int o, float v0, float v1) {
        if (n >= N) return;
        if constexpr (EPI == 4) {
            int b = n >> 10, si = n & 1023;
            fout[((size_t)b * COUT + o)     * PS + si] = v0;
            fout[((size_t)b * COUT + o + 1) * PS + si] = v1;
        } else {
            float x = v0, y = v1;
            if constexpr (EPI == 2) {
                __half2 rr = *(const __half2*)(resid + (size_t)n * COUT + o);
                x += __half2float(__low2half(rr));
                y += __half2float(__high2half(rr));
            }
            if constexpr (EPI != 3) { x = fmaxf(x, 0.f); y = fmaxf(y, 0.f); }
            if constexpr (EPI == 1) {
                __half2 rr = *(const __half2*)(resid + (size_t)n * COUT + o);
                x += __half2float(__low2half(rr));
                y += __half2float(__high2half(rr));
            }
            *(__half2*)(out + (size_t)n * COUT + o) = __floats2half2_rn(x, y);
        }
    };

#pragma unroll
    for (int mf = 0; mf < MF; mf++) {
        const int r = wm * WTM + mf * 16 + gId;
#pragma unroll
        for (int nf = 0; nf < NF; nf++) {
            const int o = nt0 + wn * WTN + nf * 8 + 2 * tig;
            emit(n0 + r,     o, acc[mf][nf][0], acc[mf][nf][1]);
            emit(n0 + r + 8, o, acc[mf][nf][2], acc[mf][nf][3]);
        }
    }
}

// ---------------- fused prep: stem conv + weight conversions + seed chains ----------------
#define SB0_N (27 * 32 * 32)
#define SD1_N (8 * 32 * 64)
#define SB1_N (27 * 64 * 64)
#define SD2_N (8 * 64 * 128)
#define SB2_N (27 * 128 * 128)
#define SD3_N (8 * 128 * 256)
#define SB3_N (27 * 256 * 256)
#define SU2_N (384 * 256)
#define SU1_N (320 * 128)
#define SU0_N (160 * 96)
#define SWO_N (96 * 512)
#define STEM_BLKS ((PN0 + 31) / 32)
#define CHAIN_BLKS (NSEED / 256)
#define NB(x) (((x) + 255) / 256)
#define PREP_BLKS (STEM_BLKS + CHAIN_BLKS + NB(SB0_N) + NB(SD1_N) + NB(SB1_N) + \
                   NB(SD2_N) + NB(SB2_N) + NB(SD3_N) + NB(SB3_N) + \
                   NB(SU2_N) + NB(SU1_N) + NB(SU0_N) + NB(SWO_N))

__device__ __forceinline__ void cvt_conv(const float* s, __half* d,
                                         int Cin, int Cout, int i, int total) {
    if (i < total) {
        int kco = Cin * Cout;
        int k = i / kco, r = i % kco;
        int c = r / Cout, o = r % Cout;
        d[((size_t)k * Cout + o) * Cin + c] = __float2half_rn(s[i]);
    }
}
__device__ __forceinline__ void cvt_lin(const float* s, __half* d,
                                        int Cin, int Cout, int i, int total) {
    if (i < total) {
        int c = i / Cout, o = i % Cout;
        d[(size_t)o * Cin + c] = __float2half_rn(s[i]);
    }
}

__global__ __launch_bounds__(256) void prep_kernel(
    const float* __restrict__ feats, const int* __restrict__ nbr0,
    const float* __restrict__ W_stem, __half* __restrict__ x0out,
    const float* Wb0, const float* Wd1, const float* Wb1, const float* Wd2,
    const float* Wb2, const float* Wd3, const float* Wb3,
    const float* Wu2, const float* Wu1, const float* Wu0, const float* Wout,
    const int* __restrict__ up0, const int* __restrict__ up1,
    const int* __restrict__ up2, const int* __restrict__ seed)
{
    __shared__ __align__(16) float As[32][3];
    __shared__ int s_idx[32 * 27];

    const int tid = threadIdx.x;
    int bid = blockIdx.x;

    if (bid < STEM_BLKS) {
        // ---- stem: 27-tap conv, CIN=3 -> C0=32, scalar fp32, fp16 out ----
        const int n0 = bid * 32;
        const int o = tid % 32;
        const int mg = tid / 32;      // 8 groups of 4 rows
        for (int i = tid; i < 32 * 27; i += 256) {
            int n = n0 + i / 27;
            s_idx[i] = (n < PN0) ? nbr0[(size_t)n0 * 27 + i] : 0;
        }
        float acc[4] = {0.f, 0.f, 0.f, 0.f};
        for (int k = 0; k < 27; k++) {
            __syncthreads();
            for (int i = tid; i < 32 * 3; i += 256) {
                int m = i / 3, c = i % 3;
                As[m][c] = __ldg(feats + (size_t)s_idx[m * 27 + k] * 3 + c);
            }
            __syncthreads();
            const float* Wk = W_stem + (size_t)k * 3 * 32;
            for (int c = 0; c < 3; c++) {
                float w = __ldg(Wk + (size_t)c * 32 + o);
#pragma unroll
                for (int mi = 0; mi < 4; mi++)
                    acc[mi] += As[mg * 4 + mi][c] * w;
            }
        }
#pragma unroll
        for (int mi = 0; mi < 4; mi++) {
            int n = n0 + mg * 4 + mi;
            if (n < PN0)
                x0out[(size_t)n * 32 + o] = __float2half_rn(fmaxf(acc[mi], 0.f));
        }
        return;
    }
    bid -= STEM_BLKS;

    if (bid < CHAIN_BLKS) {
        int i = bid * 256 + tid;
        if (i < NSEED) {
            int p = seed[i];
            int j1 = up0[p];
            int j2 = up1[j1];
            int j3 = up2[j2];
            g_chp[i] = p; g_ch1[i] = j1; g_ch2[i] = j2; g_ch3[i] = j3;
        }
        return;
    }
    bid -= CHAIN_BLKS;

    if (bid < NB(SB0_N)) { cvt_conv(Wb0, g_wb0, 32, 32,  bid * 256 + tid, SB0_N); return; }
    bid -= NB(SB0_N);
    if (bid < NB(SD1_N)) { cvt_conv(Wd1, g_wd1, 32, 64,  bid * 256 + tid, SD1_N); return; }
    bid -= NB(SD1_N);
    if (bid < NB(SB1_N)) { cvt_conv(Wb1, g_wb1, 64, 64,  bid * 256 + tid, SB1_N); return; }
    bid -= NB(SB1_N);
    if (bid < NB(SD2_N)) { cvt_conv(Wd2, g_wd2, 64, 128, bid * 256 + tid, SD2_N); return; }
    bid -= NB(SD2_N);
    if (bid < NB(SB2_N)) { cvt_conv(Wb2, g_wb2, 128, 128, bid * 256 + tid, SB2_N); return; }
    bid -= NB(SB2_N);
    if (bid < NB(SD3_N)) { cvt_conv(Wd3, g_wd3, 128, 256, bid * 256 + tid, SD3_N); return; }
    bid -= NB(SD3_N);
    if (bid < NB(SB3_N)) { cvt_conv(Wb3, g_wb3, 256, 256, bid * 256 + tid, SB3_N); return; }
    bid -= NB(SB3_N);
    if (bid < NB(SU2_N)) { cvt_lin(Wu2, g_wu2, 384, 256, bid * 256 + tid, SU2_N); return; }
    bid -= NB(SU2_N);
    if (bid < NB(SU1_N)) { cvt_lin(Wu1, g_wu1, 320, 128, bid * 256 + tid, SU1_N); return; }
    bid -= NB(SU1_N);
    if (bid < NB(SU0_N)) { cvt_lin(Wu0, g_wu0, 160, 96, bid * 256 + tid, SU0_N); return; }
    bid -= NB(SU0_N);
    if (bid < NB(SWO_N)) { cvt_lin(Wout, g_wo, 96, 512, bid * 256 + tid, SWO_N); return; }
}

// ---------------- launch ----------------
extern "C" void kernel_launch(void* const* d_in, const int* in_sizes, int n_in,
                              void* d_out, int out_size)
{
    (void)in_sizes; (void)n_in; (void)out_size;
    const float* feats   = (const float*)d_in[0];
    const int*   nbr0    = (const int*)d_in[1];
    const int*   nbr1    = (const int*)d_in[2];
    const int*   nbr2    = (const int*)d_in[3];
    const int*   nbr3    = (const int*)d_in[4];
    const int*   down1   = (const int*)d_in[5];
    const int*   down2   = (const int*)d_in[6];
    const int*   down3   = (const int*)d_in[7];
    const int*   up2     = (const int*)d_in[8];
    const int*   up1     = (const int*)d_in[9];
    const int*   up0     = (const int*)d_in[10];
    const int*   seedidx = (const int*)d_in[11];
    const float* W_stem  = (const float*)d_in[12];
    const float* W_b0    = (const float*)d_in[13];
    const float* W_d1    = (const float*)d_in[14];
    const float* W_b1    = (const float*)d_in[15];
    const float* W_d2    = (const float*)d_in[16];
    const float* W_b2    = (const float*)d_in[17];
    const float* W_d3    = (const float*)d_in[18];
    const float* W_b3    = (const float*)d_in[19];
    const float* W_u2    = (const float*)d_in[20];
    const float* W_u1    = (const float*)d_in[21];
    const float* W_u0    = (const float*)d_in[22];
    const float* W_out   = (const float*)d_in[23];

    __half *px0, *pt0, *px1, *pt1, *px2, *pt2, *px3, *pt3;
    cudaGetSymbolAddress((void**)&px0, g_x0);
    cudaGetSymbolAddress((void**)&pt0, g_t0);
    cudaGetSymbolAddress((void**)&px1, g_x1);
    cudaGetSymbolAddress((void**)&pt1, g_t1);
    cudaGetSymbolAddress((void**)&px2, g_x2);
    cudaGetSymbolAddress((void**)&pt2, g_t2);
    cudaGetSymbolAddress((void**)&px3, g_x3);
    cudaGetSymbolAddress((void**)&pt3, g_t3);

    __half *wb0, *wd1, *wb1, *wd2, *wb2, *wd3, *wb3, *wu2, *wu1, *wu0, *wo;
    cudaGetSymbolAddress((void**)&wb0, g_wb0);
    cudaGetSymbolAddress((void**)&wd1, g_wd1);
    cudaGetSymbolAddress((void**)&wb1, g_wb1);
    cudaGetSymbolAddress((void**)&wd2, g_wd2);
    cudaGetSymbolAddress((void**)&wb2, g_wb2);
    cudaGetSymbolAddress((void**)&wd3, g_wd3);
    cudaGetSymbolAddress((void**)&wb3, g_wb3);
    cudaGetSymbolAddress((void**)&wu2, g_wu2);
    cudaGetSymbolAddress((void**)&wu1, g_wu1);
    cudaGetSymbolAddress((void**)&wu0, g_wu0);
    cudaGetSymbolAddress((void**)&wo,  g_wo);

    int *chp, *ch1, *ch2, *ch3;
    cudaGetSymbolAddress((void**)&chp, g_chp);
    cudaGetSymbolAddress((void**)&ch1, g_ch1);
    cudaGetSymbolAddress((void**)&ch2, g_ch2);
    cudaGetSymbolAddress((void**)&ch3, g_ch3);

    __half *ut2, *u2b, *ut1, *u1b, *ut0, *u0b;
    cudaGetSymbolAddress((void**)&ut2, g_ut2);
    cudaGetSymbolAddress((void**)&u2b, g_u2);
    cudaGetSymbolAddress((void**)&ut1, g_ut1);
    cudaGetSymbolAddress((void**)&u1b, g_u1);
    cudaGetSymbolAddress((void**)&ut0, g_ut0);
    cudaGetSymbolAddress((void**)&u0b, g_u0);

    // smem attributes (host-side, idempotent)
    auto setsm = [](const void* fn, int b) {
        cudaFuncSetAttribute(fn, cudaFuncAttributeMaxDynamicSharedMemorySize, b);
    };
    setsm((const void*)spconv_g<27, 32, 32, 32, 0, 1>,    smem_g(32, 32));
    setsm((const void*)spconv_g<8, 32, 64, 64, 0, 0>,     smem_g(32, 64));
    setsm((const void*)spconv_g<27, 64, 64, 64, 0, 1>,    smem_g(64, 64));
    setsm((const void*)spconv_g<8, 64, 128, 128, 0, 0>,   smem_g(64, 128));
    setsm((const void*)spconv_g<27, 128, 128, 128, 0, 1>, smem_g(128, 128));
    setsm((const void*)spconv_g<8, 128, 256, 128, 0, 0>,  smem_g(128, 128));
    setsm((const void*)spconv_g<27, 256, 256, 128, 0, 1>, smem_g(256, 128));
    setsm((const void*)spconv_g<1, 256, 256, 128, 1, 3>,  smem_g(256, 128));
    setsm((const void*)spconv_g<1, 128, 256, 128, 1, 2>,  smem_g(128, 128));
    setsm((const void*)spconv_g<1, 256, 128, 128, 2, 3>,  smem_g(256, 128));
    setsm((const void*)spconv_g<1, 64, 128, 128, 1, 2>,   smem_g(64, 128));
    setsm((const void*)spconv_g<1, 128, 96, 32, 2, 3>,    smem_g(128, 32));
    setsm((const void*)spconv_g<1, 32, 96, 32, 1, 2>,     smem_g(32, 32));
    setsm((const void*)spconv_g<1, 96, 512, 128, 2, 4>,   smem_g(96, 128));

    const int gm0 = (PN0 + 127) / 128;
    const int gm1 = (PN1 + 127) / 128;
    const int gm2 = (PN2 + 127) / 128;
    const int gm3 = (PN3 + 127) / 128;
    const int gms = NSEED / 128;  // 64

    // 1) fused prep: stem + all weight cvt + seed chains
    prep_kernel<<<PREP_BLKS, 256>>>(
        feats, nbr0, W_stem, px0,
        W_b0, W_d1, W_b1, W_d2, W_b2, W_d3, W_b3,
        W_u2, W_u1, W_u0, W_out,
        up0, up1, up2, seedidx);

    // 2) encoder (fp16 tensor-core gather-GEMMs)
    spconv_g<27, 32, 32, 32, 0, 1><<<dim3(gm0, 1), 256, smem_g(32, 32)>>>(
        px0, nbr0, wb0, 32, px0, pt0, nullptr, PN0);
    spconv_g<8, 32, 64, 64, 0, 0><<<dim3(gm1, 1), 256, smem_g(32, 64)>>>(
        pt0, down1, wd1, 32, nullptr, px1, nullptr, PN1);
    spconv_g<27, 64, 64, 64, 0, 1><<<dim3(gm1, 1), 256, smem_g(64, 64)>>>(
        px1, nbr1, wb1, 64, px1, pt1, nullptr, PN1);
    spconv_g<8, 64, 128, 128, 0, 0><<<dim3(gm2, 1), 256, smem_g(64, 128)>>>(
        pt1, down2, wd2, 64, nullptr, px2, nullptr, PN2);
    spconv_g<27, 128, 128, 128, 0, 1><<<dim3(gm2, 1), 256, smem_g(128, 128)>>>(
        px2, nbr2, wb2, 128, px2, pt2, nullptr, PN2);
    spconv_g<8, 128, 256, 128, 0, 0><<<dim3(gm3, 2), 256, smem_g(128, 128)>>>(
        pt2, down3, wd3, 128, nullptr, px3, nullptr, PN3);
    spconv_g<27, 256, 256, 128, 0, 1><<<dim3(gm3, 2), 256, smem_g(256, 128)>>>(
        px3, nbr3, wb3, 256, px3, pt3, nullptr, PN3);

    // 3) decoder as gather-GEMM passes over seed chains
    // u2 = relu(x3[ch3] @ Wu2[0:256] + x2[ch2] @ Wu2[256:384])
    spconv_g<1, 256, 256, 128, 1, 3><<<dim3(gms, 2), 256, smem_g(256, 128)>>>(
        pt3, ch3, wu2, 384, nullptr, ut2, nullptr, NSEED);
    spconv_g<1, 128, 256, 128, 1, 2><<<dim3(gms, 2), 256, smem_g(128, 128)>>>(
        pt2, ch2, wu2 + 256, 384, ut2, u2b, nullptr, NSEED);
    // u1 = relu(u2 @ Wu1[0:256] + x1[ch1] @ Wu1[256:320])
    spconv_g<1, 256, 128, 128, 2, 3><<<dim3(gms, 1), 256, smem_g(256, 128)>>>(
        u2b, nullptr, wu1, 320, nullptr, ut1, nullptr, NSEED);
    spconv_g<1, 64, 128, 128, 1, 2><<<dim3(gms, 1), 256, smem_g(64, 128)>>>(
        pt1, ch1, wu1 + 256, 320, ut1, u1b, nullptr, NSEED);
    // u0 = relu(u1 @ Wu0[0:128] + x0[chp] @ Wu0[128:160])
    spconv_g<1, 128, 96, 32, 2, 3><<<dim3(gms, 3), 256, smem_g(128, 32)>>>(
        u1b, nullptr, wu0, 160, nullptr, ut0, nullptr, NSEED);
    spconv_g<1, 32, 96, 32, 1, 2><<<dim3(gms, 3), 256, smem_g(32, 32)>>>(
        pt0, chp, wu0 + 128, 160, ut0, u0b, nullptr, NSEED);
    // out[b, o, si] = u0 @ Wout  (fp32 transposed store)
    spconv_g<1, 96, 512, 128, 2, 4><<<dim3(gms, 4), 256, smem_g(96, 128)>>>(
        u0b, nullptr, wo, 96, nullptr, nullptr, (float*)d_out, NSEED);
}